// round 1
// baseline (speedup 1.0000x reference)
#include <cuda_runtime.h>
#include <cuda_bf16.h>
#include <cstdint>
#include <cstddef>

// Problem constants
#define TT 1024
#define BB 8
#define DD 1024
#define HH 16
#define DHD 64
#define FFD 4096
#define TB (TT*BB)          // 8192
#define BH (BB*HH)          // 128

// ---------------------------------------------------------------------------
// Scratch (static device globals; no allocations anywhere)
// ---------------------------------------------------------------------------
__device__ float g_ln  [(size_t)TB * DD];        // 32 MB  (LN output, reused)
__device__ float g_qkv [(size_t)TB * 3 * DD];    // 96 MB
__device__ float g_rk  [(size_t)TT * DD];        // 4 MB
__device__ float g_bd  [(size_t)BH * TT * TT];   // 512 MB (BD_pre)
__device__ float g_s   [(size_t)BH * TT * TT];   // 512 MB (scores / probs)
__device__ float g_attn[(size_t)TB * DD];        // 32 MB
__device__ float g_h1  [(size_t)TB * FFD];       // 128 MB

// ---------------------------------------------------------------------------
// LayerNorm: one block per row of [8192, 1024]
// ---------------------------------------------------------------------------
__global__ __launch_bounds__(256) void ln_kernel(
    const float* __restrict__ x, const float* __restrict__ w,
    const float* __restrict__ bparam, float* __restrict__ out)
{
    const int row = blockIdx.x;
    const int tid = threadIdx.x;
    const float4* xr = reinterpret_cast<const float4*>(x + (size_t)row * DD);
    float4 v = xr[tid];
    float s  = v.x + v.y + v.z + v.w;
    float sq = v.x*v.x + v.y*v.y + v.z*v.z + v.w*v.w;
    #pragma unroll
    for (int o = 16; o > 0; o >>= 1) {
        s  += __shfl_xor_sync(0xffffffffu, s,  o);
        sq += __shfl_xor_sync(0xffffffffu, sq, o);
    }
    __shared__ float ss[8], ssq[8];
    if ((tid & 31) == 0) { ss[tid >> 5] = s; ssq[tid >> 5] = sq; }
    __syncthreads();
    float S = 0.f, SQ = 0.f;
    #pragma unroll
    for (int i = 0; i < 8; i++) { S += ss[i]; SQ += ssq[i]; }
    const float mean = S * (1.0f / DD);
    const float var  = SQ * (1.0f / DD) - mean * mean;
    const float rstd = rsqrtf(var + 1e-5f);
    const float4 wv = reinterpret_cast<const float4*>(w)[tid];
    const float4 bv = reinterpret_cast<const float4*>(bparam)[tid];
    float4 o;
    o.x = (v.x - mean) * rstd * wv.x + bv.x;
    o.y = (v.y - mean) * rstd * wv.y + bv.y;
    o.z = (v.z - mean) * rstd * wv.z + bv.z;
    o.w = (v.w - mean) * rstd * wv.w + bv.w;
    reinterpret_cast<float4*>(out + (size_t)row * DD)[tid] = o;
}

// ---------------------------------------------------------------------------
// SGEMM: C[M,N] = A[M,K] @ B[N,K]^T   (both row-major, K contiguous)
// 128x128 tile, BK=8, 256 threads, 8x8 per thread, register prefetch.
// EPI: 0 = store, 1 = +bias, relu, 2 = +bias +res, 3 = +res
// ---------------------------------------------------------------------------
template<int EPI>
__global__ __launch_bounds__(256) void sgemm_nt(
    const float* __restrict__ A, const float* __restrict__ B,
    float* __restrict__ C, int M, int N, int K,
    const float* __restrict__ bias, const float* __restrict__ res)
{
    __shared__ float As[8][128];
    __shared__ float Bs[8][128];
    const int tid  = threadIdx.x;
    const int tm   = (tid >> 4) << 3;   // 0..120
    const int tn   = (tid & 15) << 3;   // 0..120
    const int lrow = tid >> 1;          // 0..127
    const int lk   = (tid & 1) << 2;    // 0 or 4

    const float* Ap = A + (size_t)(blockIdx.y * 128 + lrow) * K + lk;
    const float* Bp = B + (size_t)(blockIdx.x * 128 + lrow) * K + lk;

    float acc[8][8];
    #pragma unroll
    for (int i = 0; i < 8; i++)
        #pragma unroll
        for (int j = 0; j < 8; j++) acc[i][j] = 0.f;

    float4 aR = *(const float4*)Ap;
    float4 bR = *(const float4*)Bp;

    for (int k0 = 0; k0 < K; k0 += 8) {
        As[lk+0][lrow] = aR.x; As[lk+1][lrow] = aR.y;
        As[lk+2][lrow] = aR.z; As[lk+3][lrow] = aR.w;
        Bs[lk+0][lrow] = bR.x; Bs[lk+1][lrow] = bR.y;
        Bs[lk+2][lrow] = bR.z; Bs[lk+3][lrow] = bR.w;
        __syncthreads();
        if (k0 + 8 < K) {
            aR = *(const float4*)(Ap + k0 + 8);
            bR = *(const float4*)(Bp + k0 + 8);
        }
        #pragma unroll
        for (int k = 0; k < 8; k++) {
            float a[8], b[8];
            *(float4*)&a[0] = *(const float4*)&As[k][tm];
            *(float4*)&a[4] = *(const float4*)&As[k][tm + 4];
            *(float4*)&b[0] = *(const float4*)&Bs[k][tn];
            *(float4*)&b[4] = *(const float4*)&Bs[k][tn + 4];
            #pragma unroll
            for (int i = 0; i < 8; i++)
                #pragma unroll
                for (int j = 0; j < 8; j++)
                    acc[i][j] = fmaf(a[i], b[j], acc[i][j]);
        }
        __syncthreads();
    }

    const int col0 = blockIdx.x * 128 + tn;
    float bcol[8];
    if (EPI == 1 || EPI == 2) {
        #pragma unroll
        for (int j = 0; j < 8; j++) bcol[j] = bias[col0 + j];
    }
    #pragma unroll
    for (int i = 0; i < 8; i++) {
        const size_t off = (size_t)(blockIdx.y * 128 + tm + i) * N + col0;
        float o[8];
        #pragma unroll
        for (int j = 0; j < 8; j++) {
            float v = acc[i][j];
            if (EPI == 1) { v += bcol[j]; v = fmaxf(v, 0.f); }
            if (EPI == 2) { v += bcol[j] + res[off + j]; }
            if (EPI == 3) { v += res[off + j]; }
            o[j] = v;
        }
        *(float4*)(C + off)     = *(float4*)&o[0];
        *(float4*)(C + off + 4) = *(float4*)&o[4];
    }
}

// ---------------------------------------------------------------------------
// BD_pre[b,h,i,m] = sum_d (wq[i,b,h,d] + r_r_bias[h,d]) * r_k[m,h,d]
// grid: (m_tile 16, i_tile 16, bh 128); 64x64 tile, K=64
// ---------------------------------------------------------------------------
__global__ __launch_bounds__(256) void bd_kernel(
    const float* __restrict__ qkv, const float* __restrict__ rk,
    const float* __restrict__ rrbias, float* __restrict__ BD)
{
    const int bh = blockIdx.z;
    const int b = bh >> 4, h = bh & 15;
    const int i0 = blockIdx.y << 6;
    const int m0 = blockIdx.x << 6;
    __shared__ float Qs[64][64];   // [k][i]
    __shared__ float Rs[64][64];   // [k][m]
    const int tid = threadIdx.x;
    const int r  = tid >> 2;
    const int kc = (tid & 3) << 4;
    {
        const float* qp = qkv + ((size_t)(i0 + r) * BB + b) * (3 * DD) + h * DHD + kc;
        const float* bp = rrbias + h * DHD + kc;
        #pragma unroll
        for (int u = 0; u < 16; u += 4) {
            float4 v  = *(const float4*)(qp + u);
            float4 bv = *(const float4*)(bp + u);
            Qs[kc+u+0][r] = v.x + bv.x; Qs[kc+u+1][r] = v.y + bv.y;
            Qs[kc+u+2][r] = v.z + bv.z; Qs[kc+u+3][r] = v.w + bv.w;
        }
        const float* rp = rk + (size_t)(m0 + r) * DD + h * DHD + kc;
        #pragma unroll
        for (int u = 0; u < 16; u += 4) {
            float4 v = *(const float4*)(rp + u);
            Rs[kc+u+0][r] = v.x; Rs[kc+u+1][r] = v.y;
            Rs[kc+u+2][r] = v.z; Rs[kc+u+3][r] = v.w;
        }
    }
    __syncthreads();
    const int ti = (tid >> 4) << 2;
    const int tj = (tid & 15) << 2;
    float acc[4][4];
    #pragma unroll
    for (int i = 0; i < 4; i++)
        #pragma unroll
        for (int j = 0; j < 4; j++) acc[i][j] = 0.f;
    #pragma unroll 16
    for (int k = 0; k < 64; k++) {
        float4 av = *(const float4*)&Qs[k][ti];
        float4 bv = *(const float4*)&Rs[k][tj];
        float a[4] = {av.x, av.y, av.z, av.w};
        float bq[4] = {bv.x, bv.y, bv.z, bv.w};
        #pragma unroll
        for (int i = 0; i < 4; i++)
            #pragma unroll
            for (int j = 0; j < 4; j++)
                acc[i][j] = fmaf(a[i], bq[j], acc[i][j]);
    }
    #pragma unroll
    for (int i = 0; i < 4; i++) {
        const size_t off = ((size_t)bh * TT + (i0 + ti + i)) * TT + m0 + tj;
        *(float4*)(BD + off) = *(float4*)&acc[i][0];
    }
}

// ---------------------------------------------------------------------------
// S[b,h,i,j] = ( AC[i,j] + rel_shift(BD)[i,j] ) * scale
// AC[i,j] = sum_d (wq[i,b,h,d]+r_w_bias[h,d]) * wk[j,b,h,d]
// rel_shift: j<=i -> BD[i, j-i+T-1]; j==i+1 -> 0; j>i+1 -> BD[i+1, j-i-2]
// ---------------------------------------------------------------------------
__global__ __launch_bounds__(256) void ac_kernel(
    const float* __restrict__ qkv, const float* __restrict__ rwbias,
    const float* __restrict__ BD, float* __restrict__ S)
{
    const int bh = blockIdx.z;
    const int b = bh >> 4, h = bh & 15;
    const int i0 = blockIdx.y << 6;
    const int j0 = blockIdx.x << 6;
    __shared__ float Qs[64][64];
    __shared__ float Ks[64][64];
    const int tid = threadIdx.x;
    const int r  = tid >> 2;
    const int kc = (tid & 3) << 4;
    {
        const float* qp = qkv + ((size_t)(i0 + r) * BB + b) * (3 * DD) + h * DHD + kc;
        const float* bp = rwbias + h * DHD + kc;
        #pragma unroll
        for (int u = 0; u < 16; u += 4) {
            float4 v  = *(const float4*)(qp + u);
            float4 bv = *(const float4*)(bp + u);
            Qs[kc+u+0][r] = v.x + bv.x; Qs[kc+u+1][r] = v.y + bv.y;
            Qs[kc+u+2][r] = v.z + bv.z; Qs[kc+u+3][r] = v.w + bv.w;
        }
        const float* kp = qkv + ((size_t)(j0 + r) * BB + b) * (3 * DD) + DD + h * DHD + kc;
        #pragma unroll
        for (int u = 0; u < 16; u += 4) {
            float4 v = *(const float4*)(kp + u);
            Ks[kc+u+0][r] = v.x; Ks[kc+u+1][r] = v.y;
            Ks[kc+u+2][r] = v.z; Ks[kc+u+3][r] = v.w;
        }
    }
    __syncthreads();
    const int ti = (tid >> 4) << 2;
    const int tj = (tid & 15) << 2;
    float acc[4][4];
    #pragma unroll
    for (int i = 0; i < 4; i++)
        #pragma unroll
        for (int j = 0; j < 4; j++) acc[i][j] = 0.f;
    #pragma unroll 16
    for (int k = 0; k < 64; k++) {
        float4 av = *(const float4*)&Qs[k][ti];
        float4 bv = *(const float4*)&Ks[k][tj];
        float a[4] = {av.x, av.y, av.z, av.w};
        float bq[4] = {bv.x, bv.y, bv.z, bv.w};
        #pragma unroll
        for (int i = 0; i < 4; i++)
            #pragma unroll
            for (int j = 0; j < 4; j++)
                acc[i][j] = fmaf(a[i], bq[j], acc[i][j]);
    }
    const float scale = 0.125f;   // 1/sqrt(64)
    #pragma unroll
    for (int ii = 0; ii < 4; ii++) {
        const int i = i0 + ti + ii;
        const float* bdrow = BD + ((size_t)bh * TT + i) * TT;
        float o[4];
        #pragma unroll
        for (int jj = 0; jj < 4; jj++) {
            const int j = j0 + tj + jj;
            const int d = j - i;
            float bd;
            if (d <= 0)      bd = bdrow[d + (TT - 1)];
            else if (d == 1) bd = 0.f;
            else             bd = bdrow[TT + d - 2];   // row i+1
            o[jj] = (acc[ii][jj] + bd) * scale;
        }
        const size_t off = ((size_t)bh * TT + i) * TT + j0 + tj;
        *(float4*)(S + off) = *(float4*)&o[0];
    }
}

// ---------------------------------------------------------------------------
// Row softmax over 1024-wide rows of S, in place. grid = 131072
// ---------------------------------------------------------------------------
__global__ __launch_bounds__(256) void softmax_kernel(float* __restrict__ S)
{
    float* p = S + (size_t)blockIdx.x * TT;
    const int tid = threadIdx.x;
    float4 v = reinterpret_cast<float4*>(p)[tid];
    float m = fmaxf(fmaxf(v.x, v.y), fmaxf(v.z, v.w));
    #pragma unroll
    for (int o = 16; o > 0; o >>= 1) m = fmaxf(m, __shfl_xor_sync(0xffffffffu, m, o));
    __shared__ float sm[8];
    __shared__ float sSum[8];
    if ((tid & 31) == 0) sm[tid >> 5] = m;
    __syncthreads();
    float M = sm[0];
    #pragma unroll
    for (int i = 1; i < 8; i++) M = fmaxf(M, sm[i]);
    v.x = __expf(v.x - M); v.y = __expf(v.y - M);
    v.z = __expf(v.z - M); v.w = __expf(v.w - M);
    float s = v.x + v.y + v.z + v.w;
    #pragma unroll
    for (int o = 16; o > 0; o >>= 1) s += __shfl_xor_sync(0xffffffffu, s, o);
    if ((tid & 31) == 0) sSum[tid >> 5] = s;
    __syncthreads();
    float tot = 0.f;
    #pragma unroll
    for (int i = 0; i < 8; i++) tot += sSum[i];
    const float inv = 1.0f / tot;
    v.x *= inv; v.y *= inv; v.z *= inv; v.w *= inv;
    reinterpret_cast<float4*>(p)[tid] = v;
}

// ---------------------------------------------------------------------------
// attn[t,b,:][h*64+j] = sum_k P[b,h,t,k] * wv[k,b,h,j]
// grid: (i_tile 16, bh 128); 64(rows) x 64(DH) tile, K=1024 in 64-chunks
// ---------------------------------------------------------------------------
__global__ __launch_bounds__(256) void pv_kernel(
    const float* __restrict__ S, const float* __restrict__ qkv,
    float* __restrict__ attn)
{
    const int bh = blockIdx.y;
    const int b = bh >> 4, h = bh & 15;
    const int i0 = blockIdx.x << 6;
    __shared__ float Ps[64][64];   // [k][i]
    __shared__ float Vs[64][64];   // [k][j]
    const int tid = threadIdx.x;
    const int r  = tid >> 2;
    const int kc = (tid & 3) << 4;
    const int ti = (tid >> 4) << 2;
    const int tj = (tid & 15) << 2;
    float acc[4][4];
    #pragma unroll
    for (int i = 0; i < 4; i++)
        #pragma unroll
        for (int j = 0; j < 4; j++) acc[i][j] = 0.f;

    for (int k0 = 0; k0 < TT; k0 += 64) {
        __syncthreads();
        const float* pp = S + ((size_t)bh * TT + i0 + r) * TT + k0 + kc;
        #pragma unroll
        for (int u = 0; u < 16; u += 4) {
            float4 v = *(const float4*)(pp + u);
            Ps[kc+u+0][r] = v.x; Ps[kc+u+1][r] = v.y;
            Ps[kc+u+2][r] = v.z; Ps[kc+u+3][r] = v.w;
        }
        const float* vp = qkv + ((size_t)(k0 + r) * BB + b) * (3 * DD) + 2 * DD + h * DHD + kc;
        #pragma unroll
        for (int u = 0; u < 16; u += 4) {
            *(float4*)&Vs[r][kc + u] = *(const float4*)(vp + u);
        }
        __syncthreads();
        #pragma unroll 16
        for (int k = 0; k < 64; k++) {
            float4 av = *(const float4*)&Ps[k][ti];
            float4 bv = *(const float4*)&Vs[k][tj];
            float a[4] = {av.x, av.y, av.z, av.w};
            float bq[4] = {bv.x, bv.y, bv.z, bv.w};
            #pragma unroll
            for (int i = 0; i < 4; i++)
                #pragma unroll
                for (int j = 0; j < 4; j++)
                    acc[i][j] = fmaf(a[i], bq[j], acc[i][j]);
        }
    }
    #pragma unroll
    for (int i = 0; i < 4; i++) {
        const size_t off = ((size_t)(i0 + ti + i) * BB + b) * DD + h * DHD + tj;
        *(float4*)(attn + off) = *(float4*)&acc[i][0];
    }
}

// ---------------------------------------------------------------------------
// Launch
// ---------------------------------------------------------------------------
extern "C" void kernel_launch(void* const* d_in, const int* in_sizes, int n_in,
                              void* d_out, int out_size)
{
    (void)in_sizes; (void)n_in; (void)out_size;
    const float* x1      = (const float*)d_in[0];
    const float* x2      = (const float*)d_in[1];
    const float* pos     = (const float*)d_in[2];
    const float* ln1_w   = (const float*)d_in[3];
    const float* ln1_b   = (const float*)d_in[4];
    const float* qkv_w   = (const float*)d_in[5];
    const float* r_w     = (const float*)d_in[6];
    const float* r_w_b   = (const float*)d_in[7];
    const float* r_r_b   = (const float*)d_in[8];
    const float* o_w     = (const float*)d_in[9];
    const float* ln2_w   = (const float*)d_in[10];
    const float* ln2_b   = (const float*)d_in[11];
    const float* ffn_w1  = (const float*)d_in[12];
    const float* ffn_b1  = (const float*)d_in[13];
    const float* ffn_w2  = (const float*)d_in[14];
    const float* ffn_b2  = (const float*)d_in[15];

    float* out = (float*)d_out;
    float* y1 = out;
    float* y2 = out + (size_t)TB * DD;

    float *p_ln, *p_qkv, *p_rk, *p_bd, *p_s, *p_attn, *p_h1;
    cudaGetSymbolAddress((void**)&p_ln,   g_ln);
    cudaGetSymbolAddress((void**)&p_qkv,  g_qkv);
    cudaGetSymbolAddress((void**)&p_rk,   g_rk);
    cudaGetSymbolAddress((void**)&p_bd,   g_bd);
    cudaGetSymbolAddress((void**)&p_s,    g_s);
    cudaGetSymbolAddress((void**)&p_attn, g_attn);
    cudaGetSymbolAddress((void**)&p_h1,   g_h1);

    // 1. LN1(x2)
    ln_kernel<<<TB, 256>>>(x2, ln1_w, ln1_b, p_ln);
    // 2. qkv = ln @ qkv_w^T   [8192, 3072]
    sgemm_nt<0><<<dim3(3 * DD / 128, TB / 128), 256>>>(p_ln, qkv_w, p_qkv,
        TB, 3 * DD, DD, nullptr, nullptr);
    // 3. r_k = pos @ r_w^T    [1024, 1024]
    sgemm_nt<0><<<dim3(DD / 128, TT / 128), 256>>>(pos, r_w, p_rk,
        TT, DD, DD, nullptr, nullptr);
    // 4. BD_pre
    bd_kernel<<<dim3(16, 16, BH), 256>>>(p_qkv, p_rk, r_r_b, p_bd);
    // 5. S = (AC + rel_shift(BD)) * scale
    ac_kernel<<<dim3(16, 16, BH), 256>>>(p_qkv, r_w_b, p_bd, p_s);
    // 6. softmax rows
    softmax_kernel<<<BH * TT, 256>>>(p_s);
    // 7. attn = P @ V
    pv_kernel<<<dim3(16, BH), 256>>>(p_s, p_qkv, p_attn);
    // 8. y1 = attn @ o_w^T + x1
    sgemm_nt<3><<<dim3(DD / 128, TB / 128), 256>>>(p_attn, o_w, y1,
        TB, DD, DD, nullptr, x1);
    // 9. LN2(y1)
    ln_kernel<<<TB, 256>>>(y1, ln2_w, ln2_b, p_ln);
    // 10. h1 = relu(ln @ ffn_w1^T + b1)
    sgemm_nt<1><<<dim3(FFD / 128, TB / 128), 256>>>(p_ln, ffn_w1, p_h1,
        TB, FFD, DD, ffn_b1, nullptr);
    // 11. y2 = h1 @ ffn_w2^T + b2 + x2
    sgemm_nt<2><<<dim3(DD / 128, TB / 128), 256>>>(p_h1, ffn_w2, y2,
        TB, DD, FFD, ffn_b2, x2);
}

// round 2
// speedup vs baseline: 1.8005x; 1.8005x over previous
#include <cuda_runtime.h>
#include <cuda_bf16.h>
#include <cstdint>
#include <cstddef>

// Problem constants
#define TT 1024
#define BB 8
#define DD 1024
#define HH 16
#define DHD 64
#define FFD 4096
#define TB (TT*BB)          // 8192
#define BH (BB*HH)          // 128

// ---------------------------------------------------------------------------
// Scratch (static device globals; no allocations anywhere)
// ---------------------------------------------------------------------------
__device__ float g_ln  [(size_t)TB * DD];        // 32 MB (LN out; reused as V^T)
__device__ float g_qkv [(size_t)TB * 3 * DD];    // 96 MB
__device__ float g_rk  [(size_t)TT * DD];        // 4 MB
__device__ float g_bd  [(size_t)BH * TT * TT];   // 512 MB (BD_pre)
__device__ float g_s   [(size_t)BH * TT * TT];   // 512 MB (scores / probs)
__device__ float g_attn[(size_t)TB * DD];        // 32 MB
__device__ float g_h1  [(size_t)TB * FFD];       // 128 MB

// ---------------------------------------------------------------------------
// TF32 helpers
// ---------------------------------------------------------------------------
__device__ __forceinline__ uint32_t f2tf(float x){
    uint32_t u; asm("cvt.rna.tf32.f32 %0, %1;" : "=r"(u) : "f"(x)); return u;
}
__device__ __forceinline__ void mma8(float* d, const uint32_t* a, const uint32_t* b){
    asm volatile("mma.sync.aligned.m16n8k8.row.col.f32.tf32.tf32.f32 "
        "{%0,%1,%2,%3}, {%4,%5,%6,%7}, {%8,%9}, {%0,%1,%2,%3};\n"
        : "+f"(d[0]),"+f"(d[1]),"+f"(d[2]),"+f"(d[3])
        : "r"(a[0]),"r"(a[1]),"r"(a[2]),"r"(a[3]),"r"(b[0]),"r"(b[1]));
}

// ---------------------------------------------------------------------------
// Generic NT tf32 MMA mainloop: C[BMxBN] += A[BM x K] @ B[BN x K]^T
// A row stride lda, B row stride ldb (both K-contiguous). BK=16, 256 threads.
// Optional per-K bias added to A before conversion (attention Q bias).
// acc layout: [MI][NI][4] with standard m16n8 accumulator fragment mapping.
// ---------------------------------------------------------------------------
template<int BM,int BN,int WM,int WN,bool BIASK>
__device__ __forceinline__ void mma_loop(
    const float* __restrict__ A, int lda,
    const float* __restrict__ B, int ldb,
    const float* __restrict__ biasK, int K, float* acc)
{
    constexpr int BK = 16;
    constexpr int WARPS_N = BN/WN;
    constexpr int MI = WM/16, NI = WN/8;
    constexpr int AR = BM/64, BR = BN/64;
    __shared__ float As[2][BM][BK+4];
    __shared__ float Bs[2][BN][BK+4];
    const int tid  = threadIdx.x;
    const int lane = tid & 31, w = tid >> 5;
    const int wm = (w / WARPS_N) * WM;
    const int wn = (w % WARPS_N) * WN;
    const int lr = tid >> 2;            // 0..63
    const int lc = (tid & 3) << 2;      // 0,4,8,12

    float4 aR[AR], bR[BR];
    auto ldg = [&](int k0){
        #pragma unroll
        for (int u = 0; u < AR; u++){
            aR[u] = *(const float4*)(A + (size_t)(lr + 64*u)*lda + k0 + lc);
            if (BIASK){
                aR[u].x += biasK[k0+lc+0];
                aR[u].y += biasK[k0+lc+1];
                aR[u].z += biasK[k0+lc+2];
                aR[u].w += biasK[k0+lc+3];
            }
        }
        #pragma unroll
        for (int u = 0; u < BR; u++)
            bR[u] = *(const float4*)(B + (size_t)(lr + 64*u)*ldb + k0 + lc);
    };
    auto sts = [&](int buf){
        #pragma unroll
        for (int u = 0; u < AR; u++){
            float4 c;
            c.x = __uint_as_float(f2tf(aR[u].x));
            c.y = __uint_as_float(f2tf(aR[u].y));
            c.z = __uint_as_float(f2tf(aR[u].z));
            c.w = __uint_as_float(f2tf(aR[u].w));
            *(float4*)&As[buf][lr + 64*u][lc] = c;
        }
        #pragma unroll
        for (int u = 0; u < BR; u++){
            float4 c;
            c.x = __uint_as_float(f2tf(bR[u].x));
            c.y = __uint_as_float(f2tf(bR[u].y));
            c.z = __uint_as_float(f2tf(bR[u].z));
            c.w = __uint_as_float(f2tf(bR[u].w));
            *(float4*)&Bs[buf][lr + 64*u][lc] = c;
        }
    };

    ldg(0); sts(0); __syncthreads();
    int buf = 0;
    for (int k0 = 0; k0 < K; k0 += BK){
        const bool last = (k0 + BK >= K);
        if (!last) ldg(k0 + BK);
        #pragma unroll
        for (int kk = 0; kk < BK; kk += 8){
            uint32_t af[MI][4], bf[NI][2];
            const int tg = lane & 3, gr = lane >> 2;
            #pragma unroll
            for (int mi = 0; mi < MI; mi++){
                const int r = wm + mi*16 + gr;
                af[mi][0] = __float_as_uint(As[buf][r    ][kk+tg]);
                af[mi][1] = __float_as_uint(As[buf][r + 8][kk+tg]);
                af[mi][2] = __float_as_uint(As[buf][r    ][kk+tg+4]);
                af[mi][3] = __float_as_uint(As[buf][r + 8][kk+tg+4]);
            }
            #pragma unroll
            for (int ni = 0; ni < NI; ni++){
                const int c = wn + ni*8 + gr;
                bf[ni][0] = __float_as_uint(Bs[buf][c][kk+tg]);
                bf[ni][1] = __float_as_uint(Bs[buf][c][kk+tg+4]);
            }
            #pragma unroll
            for (int mi = 0; mi < MI; mi++)
                #pragma unroll
                for (int ni = 0; ni < NI; ni++)
                    mma8(acc + (mi*NI + ni)*4, af[mi], bf[ni]);
        }
        if (!last) sts(buf ^ 1);
        __syncthreads();
        buf ^= 1;
    }
}

// ---------------------------------------------------------------------------
// Dense GEMM wrapper: C[M,N] = A[M,K] @ B[N,K]^T (+ epilogue)
// EPI: 0 store, 1 +bias relu, 2 +bias +res, 3 +res
// BM=BN=128, WM=64, WN=32 (8 warps). grid (N/128, M/128)
// ---------------------------------------------------------------------------
template<int EPI>
__global__ __launch_bounds__(256, 1) void gemm128(
    const float* __restrict__ A, const float* __restrict__ B, float* __restrict__ C,
    int N, int K, const float* __restrict__ biasN, const float* __restrict__ res)
{
    float acc[64];
    #pragma unroll
    for (int i = 0; i < 64; i++) acc[i] = 0.f;
    const float* Ab = A + (size_t)blockIdx.y * 128 * K;
    const float* Bb = B + (size_t)blockIdx.x * 128 * K;
    mma_loop<128,128,64,32,false>(Ab, K, Bb, K, nullptr, K, acc);

    const int lane = threadIdx.x & 31, w = threadIdx.x >> 5;
    const int wm = (w >> 2) * 64, wn = (w & 3) * 32;
    float* Cb = C + (size_t)blockIdx.y * 128 * N + blockIdx.x * 128;
    const float* rb = res ? res + (size_t)blockIdx.y * 128 * N + blockIdx.x * 128 : nullptr;
    #pragma unroll
    for (int mi = 0; mi < 4; mi++){
        #pragma unroll
        for (int ni = 0; ni < 4; ni++){
            const float* a = acc + (mi*4 + ni)*4;
            const int r0 = wm + mi*16 + (lane >> 2);
            const int c0 = wn + ni*8 + 2*(lane & 3);
            #pragma unroll
            for (int half = 0; half < 2; half++){
                const int r = r0 + 8*half;
                float v0 = a[half*2 + 0], v1 = a[half*2 + 1];
                if (EPI == 1){
                    v0 += biasN[blockIdx.x*128 + c0];     v0 = fmaxf(v0, 0.f);
                    v1 += biasN[blockIdx.x*128 + c0 + 1]; v1 = fmaxf(v1, 0.f);
                }
                if (EPI == 2){
                    v0 += biasN[blockIdx.x*128 + c0]     + rb[(size_t)r*N + c0];
                    v1 += biasN[blockIdx.x*128 + c0 + 1] + rb[(size_t)r*N + c0 + 1];
                }
                if (EPI == 3){
                    v0 += rb[(size_t)r*N + c0];
                    v1 += rb[(size_t)r*N + c0 + 1];
                }
                float2 o = {v0, v1};
                *(float2*)(Cb + (size_t)r*N + c0) = o;
            }
        }
    }
}

// ---------------------------------------------------------------------------
// BD_pre[bh,i,m] = sum_d (wq[i,b,h,d] + r_r_bias[h,d]) * r_k[m,h,d]
// grid (8, 8, 128)
// ---------------------------------------------------------------------------
__global__ __launch_bounds__(256, 1) void bd_mma(
    const float* __restrict__ qkv, const float* __restrict__ rk,
    const float* __restrict__ rrb, float* __restrict__ BD)
{
    const int bh = blockIdx.z, b = bh >> 4, h = bh & 15;
    float acc[64];
    #pragma unroll
    for (int i = 0; i < 64; i++) acc[i] = 0.f;
    const int lda = BB * 3 * DD;
    const float* Ab = qkv + (size_t)b*(3*DD) + h*DHD + (size_t)blockIdx.y*128*lda;
    const float* Bb = rk + (size_t)blockIdx.x*128*DD + h*DHD;
    mma_loop<128,128,64,32,true>(Ab, lda, Bb, DD, rrb + h*DHD, DHD, acc);

    const int lane = threadIdx.x & 31, w = threadIdx.x >> 5;
    const int wm = (w >> 2) * 64, wn = (w & 3) * 32;
    float* Cb = BD + ((size_t)bh*TT + blockIdx.y*128)*TT + blockIdx.x*128;
    #pragma unroll
    for (int mi = 0; mi < 4; mi++)
        #pragma unroll
        for (int ni = 0; ni < 4; ni++){
            const float* a = acc + (mi*4 + ni)*4;
            const int r0 = wm + mi*16 + (lane >> 2);
            const int c0 = wn + ni*8 + 2*(lane & 3);
            #pragma unroll
            for (int half = 0; half < 2; half++){
                float2 o = {a[half*2], a[half*2 + 1]};
                *(float2*)(Cb + (size_t)(r0 + 8*half)*TT + c0) = o;
            }
        }
}

// ---------------------------------------------------------------------------
// S[bh,i,j] = (AC[i,j] + rel_shift(BD)[i,j]) * 0.125
// rel_shift: d=j-i; d<=0 -> BD[i, d+T-1]; d==1 -> 0; d>1 -> BD[i+1, d-2]
// ---------------------------------------------------------------------------
__global__ __launch_bounds__(256, 1) void ac_mma(
    const float* __restrict__ qkv, const float* __restrict__ rwb,
    const float* __restrict__ BD, float* __restrict__ S)
{
    const int bh = blockIdx.z, b = bh >> 4, h = bh & 15;
    float acc[64];
    #pragma unroll
    for (int i = 0; i < 64; i++) acc[i] = 0.f;
    const int lda = BB * 3 * DD;
    const float* Ab = qkv + (size_t)b*(3*DD) + h*DHD + (size_t)blockIdx.y*128*lda;
    const float* Bb = qkv + (size_t)b*(3*DD) + DD + h*DHD + (size_t)blockIdx.x*128*lda;
    mma_loop<128,128,64,32,true>(Ab, lda, Bb, lda, rwb + h*DHD, DHD, acc);

    const int lane = threadIdx.x & 31, w = threadIdx.x >> 5;
    const int wm = (w >> 2) * 64, wn = (w & 3) * 32;
    const int i0 = blockIdx.y * 128, j0 = blockIdx.x * 128;
    const float* bdb = BD + (size_t)bh * TT * TT;
    float* Sb = S + (size_t)bh * TT * TT;
    #pragma unroll
    for (int mi = 0; mi < 4; mi++)
        #pragma unroll
        for (int ni = 0; ni < 4; ni++){
            const float* a = acc + (mi*4 + ni)*4;
            const int r0 = wm + mi*16 + (lane >> 2);
            const int c0 = wn + ni*8 + 2*(lane & 3);
            #pragma unroll
            for (int half = 0; half < 2; half++){
                const int i = i0 + r0 + 8*half;
                float o[2];
                #pragma unroll
                for (int u = 0; u < 2; u++){
                    const int j = j0 + c0 + u;
                    const int d = j - i;
                    float bd;
                    if (d <= 0)      bd = bdb[(size_t)i*TT + d + (TT-1)];
                    else if (d == 1) bd = 0.f;
                    else             bd = bdb[(size_t)(i+1)*TT + d - 2];
                    o[u] = (a[half*2 + u] + bd) * 0.125f;
                }
                *(float2*)(Sb + (size_t)i*TT + j0 + c0) = *(float2*)o;
            }
        }
}

// ---------------------------------------------------------------------------
// V transpose: vT[bh][j][k] = qkv[(k*B+b)*3D + 2D + h*64 + j]
// grid (16 kchunks, 128 bh), 256 threads
// ---------------------------------------------------------------------------
__global__ __launch_bounds__(256) void vtrans(
    const float* __restrict__ qkv, float* __restrict__ vT)
{
    const int bh = blockIdx.y, b = bh >> 4, h = bh & 15;
    const int k0 = blockIdx.x * 64;
    __shared__ float t[64][65];
    const int tid = threadIdx.x;
    const int kr = tid >> 4;             // 0..15
    const int c4 = (tid & 15) * 4;       // 0..60
    #pragma unroll
    for (int u = 0; u < 4; u++){
        const int k = kr + u*16;
        float4 v = *(const float4*)(qkv + ((size_t)(k0 + k)*BB + b)*(3*DD) + 2*DD + h*DHD + c4);
        t[k][c4+0] = v.x; t[k][c4+1] = v.y; t[k][c4+2] = v.z; t[k][c4+3] = v.w;
    }
    __syncthreads();
    #pragma unroll
    for (int u = 0; u < 4; u++){
        const int j = kr + u*16;
        float4 o;
        o.x = t[c4+0][j]; o.y = t[c4+1][j]; o.z = t[c4+2][j]; o.w = t[c4+3][j];
        *(float4*)(vT + ((size_t)bh*DHD + j)*TT + k0 + c4) = o;
    }
}

// ---------------------------------------------------------------------------
// attn[i,b, h*64+j] = sum_k P[bh,i,k] * vT[bh,j,k]
// BM=128, BN=64, WM=32, WN=32 (8 warps: 4x2). grid (1, 8, 128)
// ---------------------------------------------------------------------------
__global__ __launch_bounds__(256, 1) void pv_mma(
    const float* __restrict__ S, const float* __restrict__ vT, float* __restrict__ attn)
{
    const int bh = blockIdx.z, b = bh >> 4, h = bh & 15;
    float acc[32];   // MI=2, NI=4
    #pragma unroll
    for (int i = 0; i < 32; i++) acc[i] = 0.f;
    const float* Ab = S + ((size_t)bh*TT + blockIdx.y*128)*TT;
    const float* Bb = vT + (size_t)bh*DHD*TT;
    mma_loop<128,64,32,32,false>(Ab, TT, Bb, TT, nullptr, TT, acc);

    const int lane = threadIdx.x & 31, w = threadIdx.x >> 5;
    const int wm = (w >> 1) * 32, wn = (w & 1) * 32;
    float* Cb = attn + ((size_t)(blockIdx.y*128)*BB + b)*DD + h*DHD;
    const int ldc = BB * DD;
    #pragma unroll
    for (int mi = 0; mi < 2; mi++)
        #pragma unroll
        for (int ni = 0; ni < 4; ni++){
            const float* a = acc + (mi*4 + ni)*4;
            const int r0 = wm + mi*16 + (lane >> 2);
            const int c0 = wn + ni*8 + 2*(lane & 3);
            #pragma unroll
            for (int half = 0; half < 2; half++){
                float2 o = {a[half*2], a[half*2 + 1]};
                *(float2*)(Cb + (size_t)(r0 + 8*half)*ldc + c0) = o;
            }
        }
}

// ---------------------------------------------------------------------------
// LayerNorm: one block per row of [8192, 1024]
// ---------------------------------------------------------------------------
__global__ __launch_bounds__(256) void ln_kernel(
    const float* __restrict__ x, const float* __restrict__ wp,
    const float* __restrict__ bparam, float* __restrict__ out)
{
    const int row = blockIdx.x;
    const int tid = threadIdx.x;
    const float4* xr = reinterpret_cast<const float4*>(x + (size_t)row * DD);
    float4 v = xr[tid];
    float s  = v.x + v.y + v.z + v.w;
    float sq = v.x*v.x + v.y*v.y + v.z*v.z + v.w*v.w;
    #pragma unroll
    for (int o = 16; o > 0; o >>= 1) {
        s  += __shfl_xor_sync(0xffffffffu, s,  o);
        sq += __shfl_xor_sync(0xffffffffu, sq, o);
    }
    __shared__ float ss[8], ssq[8];
    if ((tid & 31) == 0) { ss[tid >> 5] = s; ssq[tid >> 5] = sq; }
    __syncthreads();
    float S = 0.f, SQ = 0.f;
    #pragma unroll
    for (int i = 0; i < 8; i++) { S += ss[i]; SQ += ssq[i]; }
    const float mean = S * (1.0f / DD);
    const float var  = SQ * (1.0f / DD) - mean * mean;
    const float rstd = rsqrtf(var + 1e-5f);
    const float4 wv = reinterpret_cast<const float4*>(wp)[tid];
    const float4 bv = reinterpret_cast<const float4*>(bparam)[tid];
    float4 o;
    o.x = (v.x - mean) * rstd * wv.x + bv.x;
    o.y = (v.y - mean) * rstd * wv.y + bv.y;
    o.z = (v.z - mean) * rstd * wv.z + bv.z;
    o.w = (v.w - mean) * rstd * wv.w + bv.w;
    reinterpret_cast<float4*>(out + (size_t)row * DD)[tid] = o;
}

// ---------------------------------------------------------------------------
// Row softmax over 1024-wide rows, in place. grid = 131072
// ---------------------------------------------------------------------------
__global__ __launch_bounds__(256) void softmax_kernel(float* __restrict__ S)
{
    float* p = S + (size_t)blockIdx.x * TT;
    const int tid = threadIdx.x;
    float4 v = reinterpret_cast<float4*>(p)[tid];
    float m = fmaxf(fmaxf(v.x, v.y), fmaxf(v.z, v.w));
    #pragma unroll
    for (int o = 16; o > 0; o >>= 1) m = fmaxf(m, __shfl_xor_sync(0xffffffffu, m, o));
    __shared__ float sm[8];
    __shared__ float sSum[8];
    if ((tid & 31) == 0) sm[tid >> 5] = m;
    __syncthreads();
    float M = sm[0];
    #pragma unroll
    for (int i = 1; i < 8; i++) M = fmaxf(M, sm[i]);
    v.x = __expf(v.x - M); v.y = __expf(v.y - M);
    v.z = __expf(v.z - M); v.w = __expf(v.w - M);
    float s = v.x + v.y + v.z + v.w;
    #pragma unroll
    for (int o = 16; o > 0; o >>= 1) s += __shfl_xor_sync(0xffffffffu, s, o);
    if ((tid & 31) == 0) sSum[tid >> 5] = s;
    __syncthreads();
    float tot = 0.f;
    #pragma unroll
    for (int i = 0; i < 8; i++) tot += sSum[i];
    const float inv = 1.0f / tot;
    v.x *= inv; v.y *= inv; v.z *= inv; v.w *= inv;
    reinterpret_cast<float4*>(p)[tid] = v;
}

// ---------------------------------------------------------------------------
// Launch
// ---------------------------------------------------------------------------
extern "C" void kernel_launch(void* const* d_in, const int* in_sizes, int n_in,
                              void* d_out, int out_size)
{
    (void)in_sizes; (void)n_in; (void)out_size;
    const float* x1      = (const float*)d_in[0];
    const float* x2      = (const float*)d_in[1];
    const float* pos     = (const float*)d_in[2];
    const float* ln1_w   = (const float*)d_in[3];
    const float* ln1_b   = (const float*)d_in[4];
    const float* qkv_w   = (const float*)d_in[5];
    const float* r_w     = (const float*)d_in[6];
    const float* r_w_b   = (const float*)d_in[7];
    const float* r_r_b   = (const float*)d_in[8];
    const float* o_w     = (const float*)d_in[9];
    const float* ln2_w   = (const float*)d_in[10];
    const float* ln2_b   = (const float*)d_in[11];
    const float* ffn_w1  = (const float*)d_in[12];
    const float* ffn_b1  = (const float*)d_in[13];
    const float* ffn_w2  = (const float*)d_in[14];
    const float* ffn_b2  = (const float*)d_in[15];

    float* out = (float*)d_out;
    float* y1 = out;
    float* y2 = out + (size_t)TB * DD;

    float *p_ln, *p_qkv, *p_rk, *p_bd, *p_s, *p_attn, *p_h1;
    cudaGetSymbolAddress((void**)&p_ln,   g_ln);
    cudaGetSymbolAddress((void**)&p_qkv,  g_qkv);
    cudaGetSymbolAddress((void**)&p_rk,   g_rk);
    cudaGetSymbolAddress((void**)&p_bd,   g_bd);
    cudaGetSymbolAddress((void**)&p_s,    g_s);
    cudaGetSymbolAddress((void**)&p_attn, g_attn);
    cudaGetSymbolAddress((void**)&p_h1,   g_h1);

    // 1. LN1(x2)
    ln_kernel<<<TB, 256>>>(x2, ln1_w, ln1_b, p_ln);
    // 2. qkv = ln @ qkv_w^T   [8192, 3072]
    gemm128<0><<<dim3(24, 64), 256>>>(p_ln, qkv_w, p_qkv, 3*DD, DD, nullptr, nullptr);
    // 3. r_k = pos @ r_w^T    [1024, 1024]
    gemm128<0><<<dim3(8, 8), 256>>>(pos, r_w, p_rk, DD, DD, nullptr, nullptr);
    // 3.5 V transpose into g_ln (LN1 output no longer needed)
    vtrans<<<dim3(16, 128), 256>>>(p_qkv, p_ln);
    // 4. BD_pre
    bd_mma<<<dim3(8, 8, BH), 256>>>(p_qkv, p_rk, r_r_b, p_bd);
    // 5. S = (AC + rel_shift(BD)) * scale
    ac_mma<<<dim3(8, 8, BH), 256>>>(p_qkv, r_w_b, p_bd, p_s);
    // 6. softmax rows
    softmax_kernel<<<BH * TT, 256>>>(p_s);
    // 7. attn = P @ V
    pv_mma<<<dim3(1, 8, BH), 256>>>(p_s, p_ln, p_attn);
    // 8. y1 = attn @ o_w^T + x1
    gemm128<3><<<dim3(8, 64), 256>>>(p_attn, o_w, y1, DD, DD, nullptr, x1);
    // 9. LN2(y1)
    ln_kernel<<<TB, 256>>>(y1, ln2_w, ln2_b, p_ln);
    // 10. h1 = relu(ln @ ffn_w1^T + b1)
    gemm128<1><<<dim3(32, 64), 256>>>(p_ln, ffn_w1, p_h1, FFD, DD, ffn_b1, nullptr);
    // 11. y2 = h1 @ ffn_w2^T + b2 + x2
    gemm128<2><<<dim3(8, 64), 256>>>(p_h1, ffn_w2, y2, DD, FFD, ffn_b2, x2);
}

// round 3
// speedup vs baseline: 1.9495x; 1.0827x over previous
#include <cuda_runtime.h>
#include <cuda_bf16.h>
#include <cstdint>
#include <cstddef>

#define TT 1024
#define BB 8
#define DD 1024
#define HH 16
#define DHD 64
#define FFD 4096
#define TB (TT*BB)          // 8192
#define BH (BB*HH)          // 128

// ---------------------------------------------------------------------------
// Scratch
// ---------------------------------------------------------------------------
__device__ float g_ln  [(size_t)TB * DD];        // LN out (reused)
__device__ float g_qkv [(size_t)TB * 3 * DD];
__device__ float g_rk  [(size_t)TT * DD];
__device__ float g_bd  [(size_t)BH * TT * TT];   // 512 MB BD_pre
__device__ float g_attn[(size_t)TB * DD];
__device__ float g_h1  [(size_t)TB * FFD];
__device__ float g_qw  [(size_t)BH * TT * DHD];  // q + r_w_bias, packed [bh][i][64]
__device__ float g_qr  [(size_t)BH * TT * DHD];  // q + r_r_bias
__device__ float g_vt  [(size_t)BH * DHD * TT];  // V^T packed [bh][d][t]
__device__ float g_posr[(size_t)TT * DD];
__device__ float g_wqkv[(size_t)3 * DD * DD];
__device__ float g_wr  [(size_t)DD * DD];
__device__ float g_wo  [(size_t)DD * DD];
__device__ float g_wf1 [(size_t)FFD * DD];
__device__ float g_wf2 [(size_t)DD * FFD];

// ---------------------------------------------------------------------------
// Helpers
// ---------------------------------------------------------------------------
__device__ __forceinline__ uint32_t f2tf(float x){
    uint32_t u; asm("cvt.rna.tf32.f32 %0, %1;" : "=r"(u) : "f"(x)); return u;
}
__device__ __forceinline__ float roundtf(float x){ return __uint_as_float(f2tf(x)); }
__device__ __forceinline__ void mma8(float* d, const uint32_t* a, const uint32_t* b){
    asm volatile("mma.sync.aligned.m16n8k8.row.col.f32.tf32.tf32.f32 "
        "{%0,%1,%2,%3}, {%4,%5,%6,%7}, {%8,%9}, {%0,%1,%2,%3};\n"
        : "+f"(d[0]),"+f"(d[1]),"+f"(d[2]),"+f"(d[3])
        : "r"(a[0]),"r"(a[1]),"r"(a[2]),"r"(a[3]),"r"(b[0]),"r"(b[1]));
}
__device__ __forceinline__ void cp16(uint32_t dst, const float* src){
    asm volatile("cp.async.cg.shared.global [%0], [%1], 16;\n" :: "r"(dst), "l"(src));
}
#define CP_COMMIT() asm volatile("cp.async.commit_group;\n")
#define CP_WAIT(n)  asm volatile("cp.async.wait_group %0;\n" :: "n"(n))
__device__ __forceinline__ uint32_t s2u(const void* p){
    return (uint32_t)__cvta_generic_to_shared(p);
}
__device__ __forceinline__ uint32_t fbits(float x){ return __float_as_uint(x); }

// ---------------------------------------------------------------------------
// Elementwise tf32-round convert (float4 per thread, exact grid)
// ---------------------------------------------------------------------------
__global__ __launch_bounds__(256) void cvt_kernel(const float* __restrict__ in,
                                                  float* __restrict__ out)
{
    const int i = blockIdx.x * 256 + threadIdx.x;
    float4 v = reinterpret_cast<const float4*>(in)[i];
    v.x = roundtf(v.x); v.y = roundtf(v.y); v.z = roundtf(v.z); v.w = roundtf(v.w);
    reinterpret_cast<float4*>(out)[i] = v;
}

// ---------------------------------------------------------------------------
// Q prep: Qw[bh][i][d] = round(q + rwb), Qr = round(q + rrb). 8192 blocks x 256.
// ---------------------------------------------------------------------------
__global__ __launch_bounds__(256) void qprep_kernel(
    const float* __restrict__ qkv, const float* __restrict__ rwb,
    const float* __restrict__ rrb, float* __restrict__ Qw, float* __restrict__ Qr)
{
    const int g = blockIdx.x * 256 + threadIdx.x;       // float4 index
    const int bh = g >> 14;                             // / (1024*16)
    const int rem = g & 16383;
    const int i = rem >> 4, d4 = rem & 15;
    const int b = bh >> 4, h = bh & 15;
    float4 v = *reinterpret_cast<const float4*>(qkv + ((size_t)i*BB + b)*(3*DD) + h*DHD + d4*4);
    float4 w = reinterpret_cast<const float4*>(rwb)[h*16 + d4];
    float4 r = reinterpret_cast<const float4*>(rrb)[h*16 + d4];
    float4 ow, orr;
    ow.x = roundtf(v.x + w.x); ow.y = roundtf(v.y + w.y);
    ow.z = roundtf(v.z + w.z); ow.w = roundtf(v.w + w.w);
    orr.x = roundtf(v.x + r.x); orr.y = roundtf(v.y + r.y);
    orr.z = roundtf(v.z + r.z); orr.w = roundtf(v.w + r.w);
    reinterpret_cast<float4*>(Qw)[g] = ow;
    reinterpret_cast<float4*>(Qr)[g] = orr;
}

// ---------------------------------------------------------------------------
// V transpose: vT[bh][d][t] = qkv[(t*B+b)*3D + 2D + h*64 + d]
// ---------------------------------------------------------------------------
__global__ __launch_bounds__(256) void vtrans(
    const float* __restrict__ qkv, float* __restrict__ vT)
{
    const int bh = blockIdx.y, b = bh >> 4, h = bh & 15;
    const int k0 = blockIdx.x * 64;
    __shared__ float t[64][65];
    const int tid = threadIdx.x;
    const int kr = tid >> 4;
    const int c4 = (tid & 15) * 4;
    #pragma unroll
    for (int u = 0; u < 4; u++){
        const int k = kr + u*16;
        float4 v = *(const float4*)(qkv + ((size_t)(k0 + k)*BB + b)*(3*DD) + 2*DD + h*DHD + c4);
        t[k][c4+0] = v.x; t[k][c4+1] = v.y; t[k][c4+2] = v.z; t[k][c4+3] = v.w;
    }
    __syncthreads();
    #pragma unroll
    for (int u = 0; u < 4; u++){
        const int j = kr + u*16;
        float4 o;
        o.x = t[c4+0][j]; o.y = t[c4+1][j]; o.z = t[c4+2][j]; o.w = t[c4+3][j];
        *(float4*)(vT + ((size_t)bh*DHD + j)*TT + k0 + c4) = o;
    }
}

// ---------------------------------------------------------------------------
// cp.async 3-stage GEMM mainloop: acc[64] += A[128xK] @ B[128xK]^T
// smem layout (floats): As[3][128][20] then Bs[3][128][20]  (61440 bytes)
// ---------------------------------------------------------------------------
__device__ __forceinline__ void gemm_mainloop(
    const float* __restrict__ Ab, int lda,
    const float* __restrict__ Bb, int ldb,
    int K, float* acc, float* sm)
{
    constexpr int STG = 3;
    const int tid = threadIdx.x;
    const int lr = tid >> 1, cs = (tid & 1) * 8;
    float* As = sm;
    float* Bs = sm + STG * 2560;
    const uint32_t aBase = s2u(As), bBase = s2u(Bs);
    const float* apn = Ab + (size_t)lr * lda + cs;
    const float* bpn = Bb + (size_t)lr * ldb + cs;

    auto issue = [&](int s, int k0){
        uint32_t da = aBase + (uint32_t)(s*2560 + lr*20 + cs)*4;
        cp16(da, apn + k0); cp16(da + 16, apn + k0 + 4);
        uint32_t db = bBase + (uint32_t)(s*2560 + lr*20 + cs)*4;
        cp16(db, bpn + k0); cp16(db + 16, bpn + k0 + 4);
    };
    #pragma unroll
    for (int s = 0; s < STG-1; s++){ issue(s, s*16); CP_COMMIT(); }

    const int lane = tid & 31, w = tid >> 5;
    const int wm = (w >> 2) * 64, wn = (w & 3) * 32;
    const int gr = lane >> 2, tg = lane & 3;
    int buf = 0;
    for (int k0 = 0, t = 0; k0 < K; k0 += 16, t++){
        CP_WAIT(1);
        __syncthreads();
        const int kn = k0 + (STG-1)*16;
        if (kn < K) issue((t + STG - 1) % STG, kn);
        CP_COMMIT();
        const float* Asb = As + buf*2560;
        const float* Bsb = Bs + buf*2560;
        #pragma unroll
        for (int kk = 0; kk < 16; kk += 8){
            uint32_t af[4][4], bf[4][2];
            #pragma unroll
            for (int mi = 0; mi < 4; mi++){
                const float* p = Asb + (wm + mi*16 + gr)*20 + kk + tg;
                af[mi][0] = fbits(p[0]);   af[mi][1] = fbits(p[160]);
                af[mi][2] = fbits(p[4]);   af[mi][3] = fbits(p[164]);
            }
            #pragma unroll
            for (int ni = 0; ni < 4; ni++){
                const float* p = Bsb + (wn + ni*8 + gr)*20 + kk + tg;
                bf[ni][0] = fbits(p[0]);   bf[ni][1] = fbits(p[4]);
            }
            #pragma unroll
            for (int mi = 0; mi < 4; mi++)
                #pragma unroll
                for (int ni = 0; ni < 4; ni++)
                    mma8(acc + (mi*4 + ni)*4, af[mi], bf[ni]);
        }
        buf = (buf + 1) % STG;
    }
}

// ---------------------------------------------------------------------------
// Dense GEMM: C[M,N] = A[M,K] @ B[N,K]^T (+ epilogue). grid (N/128, M/128)
// EPI: 0 store, 1 +bias relu, 2 +bias +res, 3 +res.  ROUND: tf32-round output
// ---------------------------------------------------------------------------
template<int EPI, int ROUND>
__global__ __launch_bounds__(256, 1) void gemm_async(
    const float* __restrict__ A, const float* __restrict__ B, float* __restrict__ C,
    int N, int K, const float* __restrict__ biasN, const float* __restrict__ res)
{
    extern __shared__ float sm[];
    float acc[64];
    #pragma unroll
    for (int i = 0; i < 64; i++) acc[i] = 0.f;
    gemm_mainloop(A + (size_t)blockIdx.y*128*K, K,
                  B + (size_t)blockIdx.x*128*K, K, K, acc, sm);

    const int lane = threadIdx.x & 31, w = threadIdx.x >> 5;
    const int wm = (w >> 2) * 64, wn = (w & 3) * 32;
    float* Cb = C + (size_t)blockIdx.y*128*N + blockIdx.x*128;
    const float* rb = res ? res + (size_t)blockIdx.y*128*N + blockIdx.x*128 : nullptr;
    #pragma unroll
    for (int mi = 0; mi < 4; mi++)
        #pragma unroll
        for (int ni = 0; ni < 4; ni++){
            const float* a = acc + (mi*4 + ni)*4;
            const int r0 = wm + mi*16 + (lane >> 2);
            const int c0 = wn + ni*8 + 2*(lane & 3);
            #pragma unroll
            for (int half = 0; half < 2; half++){
                const int r = r0 + 8*half;
                float v0 = a[half*2 + 0], v1 = a[half*2 + 1];
                if (EPI == 1){
                    v0 += biasN[blockIdx.x*128 + c0];     v0 = fmaxf(v0, 0.f);
                    v1 += biasN[blockIdx.x*128 + c0 + 1]; v1 = fmaxf(v1, 0.f);
                }
                if (EPI == 2){
                    v0 += biasN[blockIdx.x*128 + c0]     + rb[(size_t)r*N + c0];
                    v1 += biasN[blockIdx.x*128 + c0 + 1] + rb[(size_t)r*N + c0 + 1];
                }
                if (EPI == 3){
                    v0 += rb[(size_t)r*N + c0];
                    v1 += rb[(size_t)r*N + c0 + 1];
                }
                if (ROUND){ v0 = roundtf(v0); v1 = roundtf(v1); }
                float2 o = {v0, v1};
                *(float2*)(Cb + (size_t)r*N + c0) = o;
            }
        }
}

// ---------------------------------------------------------------------------
// BD_pre: BD[bh][i][m] = Qr[bh][i] . rk[m][h*64..]. grid (8, 8, 128)
// ---------------------------------------------------------------------------
__global__ __launch_bounds__(256, 1) void bd_async(
    const float* __restrict__ Qr, const float* __restrict__ rk, float* __restrict__ BD)
{
    extern __shared__ float sm[];
    const int bh = blockIdx.z, h = bh & 15;
    float acc[64];
    #pragma unroll
    for (int i = 0; i < 64; i++) acc[i] = 0.f;
    gemm_mainloop(Qr + ((size_t)bh*TT + blockIdx.y*128)*DHD, DHD,
                  rk + (size_t)blockIdx.x*128*DD + h*DHD, DD, DHD, acc, sm);

    const int lane = threadIdx.x & 31, w = threadIdx.x >> 5;
    const int wm = (w >> 2) * 64, wn = (w & 3) * 32;
    float* Cb = BD + ((size_t)bh*TT + blockIdx.y*128)*TT + blockIdx.x*128;
    #pragma unroll
    for (int mi = 0; mi < 4; mi++)
        #pragma unroll
        for (int ni = 0; ni < 4; ni++){
            const float* a = acc + (mi*4 + ni)*4;
            const int r0 = wm + mi*16 + (lane >> 2);
            const int c0 = wn + ni*8 + 2*(lane & 3);
            #pragma unroll
            for (int half = 0; half < 2; half++){
                float2 o = {a[half*2], a[half*2 + 1]};
                *(float2*)(Cb + (size_t)(r0 + 8*half)*TT + c0) = o;
            }
        }
}

// ---------------------------------------------------------------------------
// Fused flash attention with rel-shift.
// grid (8 i-tiles, 128 bh), 256 threads. i-tile = 128 rows, warp = 16 rows.
// smem floats: Qs[128*68]=8704 | Ks[2][128*68]=17408 | Vs[64*132]=8448 | Ps[128*132]=16896
// total 51456 floats = 205824 B
// ---------------------------------------------------------------------------
__global__ __launch_bounds__(256, 1) void flash_attn(
    const float* __restrict__ Qw, const float* __restrict__ qkv,
    const float* __restrict__ vT, const float* __restrict__ BD,
    float* __restrict__ attn)
{
    extern __shared__ float sm[];
    float* Qs = sm;                 // [128][68]
    float* Ks = sm + 8704;          // [2][128][68]
    float* Vs = sm + 26112;         // [64][132]
    float* Ps = sm + 34560;         // [128][132]
    const uint32_t qB = s2u(Qs), kB = s2u(Ks), vB = s2u(Vs);

    const int bh = blockIdx.y, b = bh >> 4, h = bh & 15;
    const int i0 = blockIdx.x * 128;
    const int tid = threadIdx.x, lane = tid & 31, w = tid >> 5;
    const int gr = lane >> 2, tg = lane & 3;
    const int wm = w * 16;

    // copy mappings
    const int klr = tid >> 1, kc0 = (tid & 1) * 32;      // Q/K: 128 rows x 64
    const int vr  = tid >> 2, vc0 = (tid & 3) * 32;      // V: 64 rows x 128

    const float* Qsrc = Qw + ((size_t)bh*TT + i0 + klr)*DHD + kc0;
    const float* Ksrc = qkv + ((size_t)klr*BB + b)*(3*DD) + DD + h*DHD + kc0;   // + jt*128 rows
    const size_t kRowStride = (size_t)BB*3*DD;
    const float* Vsrc = vT + ((size_t)bh*DHD + vr)*TT + vc0;                     // + jt*128 cols

    auto issueQ = [&](){
        uint32_t d = qB + (uint32_t)(klr*68 + kc0)*4;
        #pragma unroll
        for (int u = 0; u < 8; u++) cp16(d + u*16, Qsrc + u*4);
    };
    auto issueK = [&](int slot, int jt){
        if (jt < 8){
            const float* src = Ksrc + (size_t)jt*128*kRowStride;
            uint32_t d = kB + (uint32_t)(slot*8704 + klr*68 + kc0)*4;
            #pragma unroll
            for (int u = 0; u < 8; u++) cp16(d + u*16, src + u*4);
        }
    };
    auto issueV = [&](int jt){
        if (jt < 8){
            const float* src = Vsrc + jt*128;
            uint32_t d = vB + (uint32_t)(vr*132 + vc0)*4;
            #pragma unroll
            for (int u = 0; u < 8; u++) cp16(d + u*16, src + u*4);
        }
    };

    issueQ(); issueK(0, 0); CP_COMMIT();
    issueV(0);              CP_COMMIT();
    issueK(1, 1);           CP_COMMIT();

    float m_lo = -1e30f, m_hi = -1e30f, l_lo = 0.f, l_hi = 0.f;
    float acc_o[8][4];
    #pragma unroll
    for (int i = 0; i < 8; i++)
        #pragma unroll
        for (int e = 0; e < 4; e++) acc_o[i][e] = 0.f;

    const float* bdb = BD + (size_t)bh * TT * TT;
    const int i_lo = i0 + wm + gr, i_hi = i_lo + 8;

    for (int t = 0; t < 8; t++){
        CP_WAIT(2);
        __syncthreads();
        // ---- scores: S = Q @ K^T over K=64 ----
        float acc_s[16][4];
        #pragma unroll
        for (int ni = 0; ni < 16; ni++)
            #pragma unroll
            for (int e = 0; e < 4; e++) acc_s[ni][e] = 0.f;
        const float* Ksb = Ks + (t & 1)*8704;
        #pragma unroll
        for (int kk = 0; kk < 64; kk += 8){
            uint32_t af[4];
            const float* qp = Qs + (wm + gr)*68 + kk + tg;
            af[0] = fbits(qp[0]);   af[1] = fbits(qp[544]);
            af[2] = fbits(qp[4]);   af[3] = fbits(qp[548]);
            #pragma unroll
            for (int ni = 0; ni < 16; ni++){
                const float* kp = Ksb + (ni*8 + gr)*68 + kk + tg;
                uint32_t bf[2] = { fbits(kp[0]), fbits(kp[4]) };
                mma8(acc_s[ni], af, bf);
            }
        }
        // ---- rel-shift BD add + scale + online softmax ----
        const int j0 = t * 128;
        float smax_lo = -1e30f, smax_hi = -1e30f;
        #pragma unroll
        for (int ni = 0; ni < 16; ni++){
            #pragma unroll
            for (int e = 0; e < 4; e++){
                const int i = (e < 2) ? i_lo : i_hi;
                const int j = j0 + ni*8 + 2*tg + (e & 1);
                const int d = j - i;
                float bd;
                if (d <= 0)      bd = bdb[(size_t)i*TT + d + (TT-1)];
                else if (d == 1) bd = 0.f;
                else             bd = bdb[(size_t)(i+1)*TT + d - 2];
                const float v = (acc_s[ni][e] + bd) * 0.125f;
                acc_s[ni][e] = v;
                if (e < 2) smax_lo = fmaxf(smax_lo, v);
                else       smax_hi = fmaxf(smax_hi, v);
            }
        }
        smax_lo = fmaxf(smax_lo, __shfl_xor_sync(0xffffffffu, smax_lo, 1));
        smax_lo = fmaxf(smax_lo, __shfl_xor_sync(0xffffffffu, smax_lo, 2));
        smax_hi = fmaxf(smax_hi, __shfl_xor_sync(0xffffffffu, smax_hi, 1));
        smax_hi = fmaxf(smax_hi, __shfl_xor_sync(0xffffffffu, smax_hi, 2));
        const float mn_lo = fmaxf(m_lo, smax_lo);
        const float mn_hi = fmaxf(m_hi, smax_hi);
        const float corr_lo = __expf(m_lo - mn_lo);
        const float corr_hi = __expf(m_hi - mn_hi);
        m_lo = mn_lo; m_hi = mn_hi;
        float ls_lo = 0.f, ls_hi = 0.f;
        #pragma unroll
        for (int ni = 0; ni < 16; ni++){
            float p0 = __expf(acc_s[ni][0] - mn_lo);
            float p1 = __expf(acc_s[ni][1] - mn_lo);
            float p2 = __expf(acc_s[ni][2] - mn_hi);
            float p3 = __expf(acc_s[ni][3] - mn_hi);
            ls_lo += p0 + p1; ls_hi += p2 + p3;
            float2 lo = { roundtf(p0), roundtf(p1) };
            float2 hi = { roundtf(p2), roundtf(p3) };
            *(float2*)(Ps + (wm + gr)*132 + ni*8 + 2*tg)     = lo;
            *(float2*)(Ps + (wm + gr + 8)*132 + ni*8 + 2*tg) = hi;
        }
        l_lo = l_lo * corr_lo + ls_lo;
        l_hi = l_hi * corr_hi + ls_hi;
        #pragma unroll
        for (int ni = 0; ni < 8; ni++){
            acc_o[ni][0] *= corr_lo; acc_o[ni][1] *= corr_lo;
            acc_o[ni][2] *= corr_hi; acc_o[ni][3] *= corr_hi;
        }
        __syncwarp();
        CP_WAIT(1);
        __syncthreads();
        // ---- PV: O += P @ V^T over K=128 ----
        #pragma unroll
        for (int kk = 0; kk < 128; kk += 8){
            uint32_t af[4];
            const float* pp = Ps + (wm + gr)*132 + kk + tg;
            af[0] = fbits(pp[0]);    af[1] = fbits(pp[1056]);
            af[2] = fbits(pp[4]);    af[3] = fbits(pp[1060]);
            #pragma unroll
            for (int ni = 0; ni < 8; ni++){
                const float* vp = Vs + (ni*8 + gr)*132 + kk + tg;
                uint32_t bf[2] = { fbits(vp[0]), fbits(vp[4]) };
                mma8(acc_o[ni], af, bf);
            }
        }
        __syncthreads();
        issueV(t + 1);        CP_COMMIT();
        issueK(t & 1, t + 2); CP_COMMIT();
    }

    // final: normalize rows, round, store
    l_lo += __shfl_xor_sync(0xffffffffu, l_lo, 1);
    l_lo += __shfl_xor_sync(0xffffffffu, l_lo, 2);
    l_hi += __shfl_xor_sync(0xffffffffu, l_hi, 1);
    l_hi += __shfl_xor_sync(0xffffffffu, l_hi, 2);
    const float inv_lo = 1.0f / l_lo, inv_hi = 1.0f / l_hi;
    float* out_lo = attn + ((size_t)i_lo*BB + b)*DD + h*DHD;
    float* out_hi = attn + ((size_t)i_hi*BB + b)*DD + h*DHD;
    #pragma unroll
    for (int ni = 0; ni < 8; ni++){
        const int c = ni*8 + 2*tg;
        float2 lo = { roundtf(acc_o[ni][0]*inv_lo), roundtf(acc_o[ni][1]*inv_lo) };
        float2 hi = { roundtf(acc_o[ni][2]*inv_hi), roundtf(acc_o[ni][3]*inv_hi) };
        *(float2*)(out_lo + c) = lo;
        *(float2*)(out_hi + c) = hi;
    }
}

// ---------------------------------------------------------------------------
// LayerNorm (tf32-rounded output)
// ---------------------------------------------------------------------------
__global__ __launch_bounds__(256) void ln_kernel(
    const float* __restrict__ x, const float* __restrict__ wp,
    const float* __restrict__ bparam, float* __restrict__ out)
{
    const int row = blockIdx.x;
    const int tid = threadIdx.x;
    const float4* xr = reinterpret_cast<const float4*>(x + (size_t)row * DD);
    float4 v = xr[tid];
    float s  = v.x + v.y + v.z + v.w;
    float sq = v.x*v.x + v.y*v.y + v.z*v.z + v.w*v.w;
    #pragma unroll
    for (int o = 16; o > 0; o >>= 1) {
        s  += __shfl_xor_sync(0xffffffffu, s,  o);
        sq += __shfl_xor_sync(0xffffffffu, sq, o);
    }
    __shared__ float ss[8], ssq[8];
    if ((tid & 31) == 0) { ss[tid >> 5] = s; ssq[tid >> 5] = sq; }
    __syncthreads();
    float S = 0.f, SQ = 0.f;
    #pragma unroll
    for (int i = 0; i < 8; i++) { S += ss[i]; SQ += ssq[i]; }
    const float mean = S * (1.0f / DD);
    const float var  = SQ * (1.0f / DD) - mean * mean;
    const float rstd = rsqrtf(var + 1e-5f);
    const float4 wv = reinterpret_cast<const float4*>(wp)[tid];
    const float4 bv = reinterpret_cast<const float4*>(bparam)[tid];
    float4 o;
    o.x = roundtf((v.x - mean) * rstd * wv.x + bv.x);
    o.y = roundtf((v.y - mean) * rstd * wv.y + bv.y);
    o.z = roundtf((v.z - mean) * rstd * wv.z + bv.z);
    o.w = roundtf((v.w - mean) * rstd * wv.w + bv.w);
    reinterpret_cast<float4*>(out + (size_t)row * DD)[tid] = o;
}

// ---------------------------------------------------------------------------
// Launch
// ---------------------------------------------------------------------------
extern "C" void kernel_launch(void* const* d_in, const int* in_sizes, int n_in,
                              void* d_out, int out_size)
{
    (void)in_sizes; (void)n_in; (void)out_size;
    const float* x1      = (const float*)d_in[0];
    const float* x2      = (const float*)d_in[1];
    const float* pos     = (const float*)d_in[2];
    const float* ln1_w   = (const float*)d_in[3];
    const float* ln1_b   = (const float*)d_in[4];
    const float* qkv_w   = (const float*)d_in[5];
    const float* r_w     = (const float*)d_in[6];
    const float* r_w_b   = (const float*)d_in[7];
    const float* r_r_b   = (const float*)d_in[8];
    const float* o_w     = (const float*)d_in[9];
    const float* ln2_w   = (const float*)d_in[10];
    const float* ln2_b   = (const float*)d_in[11];
    const float* ffn_w1  = (const float*)d_in[12];
    const float* ffn_b1  = (const float*)d_in[13];
    const float* ffn_w2  = (const float*)d_in[14];
    const float* ffn_b2  = (const float*)d_in[15];

    float* out = (float*)d_out;
    float* y1 = out;
    float* y2 = out + (size_t)TB * DD;

    float *p_ln, *p_qkv, *p_rk, *p_bd, *p_attn, *p_h1;
    float *p_qw, *p_qr, *p_vt, *p_posr, *p_wqkv, *p_wr, *p_wo, *p_wf1, *p_wf2;
    cudaGetSymbolAddress((void**)&p_ln,   g_ln);
    cudaGetSymbolAddress((void**)&p_qkv,  g_qkv);
    cudaGetSymbolAddress((void**)&p_rk,   g_rk);
    cudaGetSymbolAddress((void**)&p_bd,   g_bd);
    cudaGetSymbolAddress((void**)&p_attn, g_attn);
    cudaGetSymbolAddress((void**)&p_h1,   g_h1);
    cudaGetSymbolAddress((void**)&p_qw,   g_qw);
    cudaGetSymbolAddress((void**)&p_qr,   g_qr);
    cudaGetSymbolAddress((void**)&p_vt,   g_vt);
    cudaGetSymbolAddress((void**)&p_posr, g_posr);
    cudaGetSymbolAddress((void**)&p_wqkv, g_wqkv);
    cudaGetSymbolAddress((void**)&p_wr,   g_wr);
    cudaGetSymbolAddress((void**)&p_wo,   g_wo);
    cudaGetSymbolAddress((void**)&p_wf1,  g_wf1);
    cudaGetSymbolAddress((void**)&p_wf2,  g_wf2);

    // opt-in smem sizes
    const int GEMM_SMEM  = 61440;
    const int FLASH_SMEM = 205824;
    cudaFuncSetAttribute(gemm_async<0,1>, cudaFuncAttributeMaxDynamicSharedMemorySize, GEMM_SMEM);
    cudaFuncSetAttribute(gemm_async<1,1>, cudaFuncAttributeMaxDynamicSharedMemorySize, GEMM_SMEM);
    cudaFuncSetAttribute(gemm_async<2,0>, cudaFuncAttributeMaxDynamicSharedMemorySize, GEMM_SMEM);
    cudaFuncSetAttribute(gemm_async<3,0>, cudaFuncAttributeMaxDynamicSharedMemorySize, GEMM_SMEM);
    cudaFuncSetAttribute(bd_async,        cudaFuncAttributeMaxDynamicSharedMemorySize, GEMM_SMEM);
    cudaFuncSetAttribute(flash_attn,      cudaFuncAttributeMaxDynamicSharedMemorySize, FLASH_SMEM);

    // 0. weight/pos tf32 pre-round
    cvt_kernel<<<3072, 256>>>(qkv_w,  p_wqkv);
    cvt_kernel<<<1024, 256>>>(r_w,    p_wr);
    cvt_kernel<<<1024, 256>>>(o_w,    p_wo);
    cvt_kernel<<<4096, 256>>>(ffn_w1, p_wf1);
    cvt_kernel<<<4096, 256>>>(ffn_w2, p_wf2);
    cvt_kernel<<<1024, 256>>>(pos,    p_posr);
    // 1. LN1(x2) (rounded)
    ln_kernel<<<TB, 256>>>(x2, ln1_w, ln1_b, p_ln);
    // 2. qkv = ln @ qkv_w^T (rounded)
    gemm_async<0,1><<<dim3(24, 64), 256, GEMM_SMEM>>>(p_ln, p_wqkv, p_qkv, 3*DD, DD, nullptr, nullptr);
    // 3. r_k = pos @ r_w^T (rounded)
    gemm_async<0,1><<<dim3(8, 8), 256, GEMM_SMEM>>>(p_posr, p_wr, p_rk, DD, DD, nullptr, nullptr);
    // 4. Q prep (+biases, rounded) and V transpose
    qprep_kernel<<<8192, 256>>>(p_qkv, r_w_b, r_r_b, p_qw, p_qr);
    vtrans<<<dim3(16, 128), 256>>>(p_qkv, p_vt);
    // 5. BD_pre
    bd_async<<<dim3(8, 8, BH), 256, GEMM_SMEM>>>(p_qr, p_rk, p_bd);
    // 6. fused attention -> attn (rounded)
    flash_attn<<<dim3(8, BH), 256, FLASH_SMEM>>>(p_qw, p_qkv, p_vt, p_bd, p_attn);
    // 7. y1 = attn @ o_w^T + x1
    gemm_async<3,0><<<dim3(8, 64), 256, GEMM_SMEM>>>(p_attn, p_wo, y1, DD, DD, nullptr, x1);
    // 8. LN2(y1) (rounded)
    ln_kernel<<<TB, 256>>>(y1, ln2_w, ln2_b, p_ln);
    // 9. h1 = relu(ln @ ffn_w1^T + b1) (rounded)
    gemm_async<1,1><<<dim3(32, 64), 256, GEMM_SMEM>>>(p_ln, p_wf1, p_h1, FFD, DD, ffn_b1, nullptr);
    // 10. y2 = h1 @ ffn_w2^T + b2 + x2
    gemm_async<2,0><<<dim3(8, 64), 256, GEMM_SMEM>>>(p_h1, p_wf2, y2, DD, FFD, ffn_b2, x2);
}

// round 4
// speedup vs baseline: 2.1675x; 1.1119x over previous
#include <cuda_runtime.h>
#include <cuda_bf16.h>
#include <cstdint>
#include <cstddef>

#define TT 1024
#define BB 8
#define DD 1024
#define HH 16
#define DHD 64
#define FFD 4096
#define TB (TT*BB)          // 8192
#define BH (BB*HH)          // 128

// ---------------------------------------------------------------------------
// Scratch
// ---------------------------------------------------------------------------
__device__ float g_ln  [(size_t)TB * DD];
__device__ float g_qkv [(size_t)TB * 3 * DD];
__device__ float g_rk  [(size_t)TT * DD];
__device__ float g_bd  [(size_t)BH * TT * TT];
__device__ float g_attn[(size_t)TB * DD];
__device__ float g_h1  [(size_t)TB * FFD];
__device__ float g_qw  [(size_t)BH * TT * DHD];
__device__ float g_qr  [(size_t)BH * TT * DHD];
__device__ float g_vt  [(size_t)BH * DHD * TT];
__device__ float g_posr[(size_t)TT * DD];
__device__ float g_wqkv[(size_t)3 * DD * DD];
__device__ float g_wr  [(size_t)DD * DD];
__device__ float g_wo  [(size_t)DD * DD];
__device__ float g_wf1 [(size_t)FFD * DD];
__device__ float g_wf2 [(size_t)DD * FFD];

// ---------------------------------------------------------------------------
// Helpers
// ---------------------------------------------------------------------------
__device__ __forceinline__ uint32_t f2tf(float x){
    uint32_t u; asm("cvt.rna.tf32.f32 %0, %1;" : "=r"(u) : "f"(x)); return u;
}
__device__ __forceinline__ float roundtf(float x){ return __uint_as_float(f2tf(x)); }
__device__ __forceinline__ void mma8(float* d, const uint32_t* a, const uint32_t* b){
    asm volatile("mma.sync.aligned.m16n8k8.row.col.f32.tf32.tf32.f32 "
        "{%0,%1,%2,%3}, {%4,%5,%6,%7}, {%8,%9}, {%0,%1,%2,%3};\n"
        : "+f"(d[0]),"+f"(d[1]),"+f"(d[2]),"+f"(d[3])
        : "r"(a[0]),"r"(a[1]),"r"(a[2]),"r"(a[3]),"r"(b[0]),"r"(b[1]));
}
// ldmatrix x4 on tf32 data aliased as b16: gives 4 8x4-tf32 tiles in mma frag layout
__device__ __forceinline__ void ldm4(uint32_t* r, uint32_t addr){
    asm volatile("ldmatrix.sync.aligned.m8n8.x4.shared.b16 {%0,%1,%2,%3}, [%4];"
        : "=r"(r[0]),"=r"(r[1]),"=r"(r[2]),"=r"(r[3]) : "r"(addr));
}
__device__ __forceinline__ void cp16(uint32_t dst, const float* src){
    asm volatile("cp.async.cg.shared.global [%0], [%1], 16;\n" :: "r"(dst), "l"(src));
}
#define CP_COMMIT() asm volatile("cp.async.commit_group;\n")
#define CP_WAIT(n)  asm volatile("cp.async.wait_group %0;\n" :: "n"(n))
__device__ __forceinline__ uint32_t s2u(const void* p){
    return (uint32_t)__cvta_generic_to_shared(p);
}

// ---------------------------------------------------------------------------
// Fused tf32-round convert for all weights + pos (one launch)
// ---------------------------------------------------------------------------
struct CvtArgs { const float* src[6]; float* dst[6]; };
__global__ __launch_bounds__(256) void cvt_multi(CvtArgs a)
{
    // float4 counts: qkv_w 786432 | r_w 262144 | o_w 262144 | f1 1048576 | f2 1048576 | pos 262144
    const int g = blockIdx.x * 256 + threadIdx.x;
    int idx = g, r = 0;
    if      (idx < 786432)  { r = 0; }
    else if (idx < 1048576) { r = 1; idx -= 786432; }
    else if (idx < 1310720) { r = 2; idx -= 1048576; }
    else if (idx < 2359296) { r = 3; idx -= 1310720; }
    else if (idx < 3407872) { r = 4; idx -= 2359296; }
    else                    { r = 5; idx -= 3407872; }
    float4 v = reinterpret_cast<const float4*>(a.src[r])[idx];
    v.x = roundtf(v.x); v.y = roundtf(v.y); v.z = roundtf(v.z); v.w = roundtf(v.w);
    reinterpret_cast<float4*>(a.dst[r])[idx] = v;
}

// ---------------------------------------------------------------------------
// Q prep: Qw = round(q + rwb), Qr = round(q + rrb), packed [bh][i][64]
// ---------------------------------------------------------------------------
__global__ __launch_bounds__(256) void qprep_kernel(
    const float* __restrict__ qkv, const float* __restrict__ rwb,
    const float* __restrict__ rrb, float* __restrict__ Qw, float* __restrict__ Qr)
{
    const int g = blockIdx.x * 256 + threadIdx.x;
    const int bh = g >> 14;
    const int rem = g & 16383;
    const int i = rem >> 4, d4 = rem & 15;
    const int b = bh >> 4, h = bh & 15;
    float4 v = *reinterpret_cast<const float4*>(qkv + ((size_t)i*BB + b)*(3*DD) + h*DHD + d4*4);
    float4 w = reinterpret_cast<const float4*>(rwb)[h*16 + d4];
    float4 r = reinterpret_cast<const float4*>(rrb)[h*16 + d4];
    float4 ow, orr;
    ow.x = roundtf(v.x + w.x); ow.y = roundtf(v.y + w.y);
    ow.z = roundtf(v.z + w.z); ow.w = roundtf(v.w + w.w);
    orr.x = roundtf(v.x + r.x); orr.y = roundtf(v.y + r.y);
    orr.z = roundtf(v.z + r.z); orr.w = roundtf(v.w + r.w);
    reinterpret_cast<float4*>(Qw)[g] = ow;
    reinterpret_cast<float4*>(Qr)[g] = orr;
}

// ---------------------------------------------------------------------------
// V transpose: vT[bh][d][t]
// ---------------------------------------------------------------------------
__global__ __launch_bounds__(256) void vtrans(
    const float* __restrict__ qkv, float* __restrict__ vT)
{
    const int bh = blockIdx.y, b = bh >> 4, h = bh & 15;
    const int k0 = blockIdx.x * 64;
    __shared__ float t[64][65];
    const int tid = threadIdx.x;
    const int kr = tid >> 4;
    const int c4 = (tid & 15) * 4;
    #pragma unroll
    for (int u = 0; u < 4; u++){
        const int k = kr + u*16;
        float4 v = *(const float4*)(qkv + ((size_t)(k0 + k)*BB + b)*(3*DD) + 2*DD + h*DHD + c4);
        t[k][c4+0] = v.x; t[k][c4+1] = v.y; t[k][c4+2] = v.z; t[k][c4+3] = v.w;
    }
    __syncthreads();
    #pragma unroll
    for (int u = 0; u < 4; u++){
        const int j = kr + u*16;
        float4 o;
        o.x = t[c4+0][j]; o.y = t[c4+1][j]; o.z = t[c4+2][j]; o.w = t[c4+3][j];
        *(float4*)(vT + ((size_t)bh*DHD + j)*TT + k0 + c4) = o;
    }
}

// ---------------------------------------------------------------------------
// 4-stage cp.async GEMM mainloop with ldmatrix fragments.
// acc[64] += A[128xK] @ B[128xK]^T. smem: As[4][128][20] | Bs[4][128][20]
// = 20480 floats = 81920 B
// ---------------------------------------------------------------------------
__device__ __forceinline__ void gemm_mainloop(
    const float* __restrict__ Ab, int lda,
    const float* __restrict__ Bb, int ldb,
    int K, float* acc, float* sm)
{
    const int tid = threadIdx.x;
    const int lr = tid >> 1, cs = (tid & 1) * 8;
    float* As = sm;
    float* Bs = sm + 4 * 2560;
    const uint32_t aBase = s2u(As), bBase = s2u(Bs);
    const float* apn = Ab + (size_t)lr * lda + cs;
    const float* bpn = Bb + (size_t)lr * ldb + cs;

    auto issue = [&](int s, int k0){
        uint32_t da = aBase + (uint32_t)(s*2560 + lr*20 + cs)*4;
        cp16(da, apn + k0); cp16(da + 16, apn + k0 + 4);
        uint32_t db = bBase + (uint32_t)(s*2560 + lr*20 + cs)*4;
        cp16(db, bpn + k0); cp16(db + 16, bpn + k0 + 4);
    };
    #pragma unroll
    for (int s = 0; s < 3; s++){
        if (s*16 < K) issue(s, s*16);
        CP_COMMIT();
    }

    const int lane = tid & 31, w = tid >> 5;
    const int wm = (w >> 2) * 64, wn = (w & 3) * 32;
    // ldmatrix lane address components
    const int arow = (lane & 7) + ((lane >> 3) & 1)*8;
    const int acol = (lane >> 4) * 4;
    const int brow = (lane & 7) + ((lane >> 4) & 1)*8;
    const int bcol = ((lane >> 3) & 1) * 4;
    const uint32_t aFrag = aBase + (uint32_t)((wm + arow)*20 + acol)*4;
    const uint32_t bFrag = bBase + (uint32_t)((wn + brow)*20 + bcol)*4;

    for (int k0 = 0, t = 0; k0 < K; k0 += 16, t++){
        CP_WAIT(2);
        __syncthreads();
        const int kn = k0 + 48;
        if (kn < K) issue((t + 3) & 3, kn);
        CP_COMMIT();
        const uint32_t aB = aFrag + (t & 3)*10240;
        const uint32_t bB = bFrag + (t & 3)*10240;
        #pragma unroll
        for (int kk = 0; kk < 16; kk += 8){
            uint32_t af[4][4], bf[4][2];
            #pragma unroll
            for (int mi = 0; mi < 4; mi++)
                ldm4(af[mi], aB + (uint32_t)(mi*16*20 + kk)*4);
            #pragma unroll
            for (int p = 0; p < 2; p++){
                uint32_t q[4];
                ldm4(q, bB + (uint32_t)(p*16*20 + kk)*4);
                bf[2*p][0] = q[0]; bf[2*p][1] = q[1];
                bf[2*p+1][0] = q[2]; bf[2*p+1][1] = q[3];
            }
            #pragma unroll
            for (int mi = 0; mi < 4; mi++)
                #pragma unroll
                for (int ni = 0; ni < 4; ni++)
                    mma8(acc + (mi*4 + ni)*4, af[mi], bf[ni]);
        }
    }
}

// ---------------------------------------------------------------------------
// Dense GEMM. EPI: 0 store, 1 +bias relu, 2 +bias +res, 3 +res. ROUND: tf32 out
// ---------------------------------------------------------------------------
template<int EPI, int ROUND>
__global__ __launch_bounds__(256, 1) void gemm_async(
    const float* __restrict__ A, const float* __restrict__ B, float* __restrict__ C,
    int N, int K, const float* __restrict__ biasN, const float* __restrict__ res)
{
    extern __shared__ float sm[];
    float acc[64];
    #pragma unroll
    for (int i = 0; i < 64; i++) acc[i] = 0.f;
    gemm_mainloop(A + (size_t)blockIdx.y*128*K, K,
                  B + (size_t)blockIdx.x*128*K, K, K, acc, sm);

    const int lane = threadIdx.x & 31, w = threadIdx.x >> 5;
    const int wm = (w >> 2) * 64, wn = (w & 3) * 32;
    float* Cb = C + (size_t)blockIdx.y*128*N + blockIdx.x*128;
    const float* rb = res ? res + (size_t)blockIdx.y*128*N + blockIdx.x*128 : nullptr;
    #pragma unroll
    for (int mi = 0; mi < 4; mi++)
        #pragma unroll
        for (int ni = 0; ni < 4; ni++){
            const float* a = acc + (mi*4 + ni)*4;
            const int r0 = wm + mi*16 + (lane >> 2);
            const int c0 = wn + ni*8 + 2*(lane & 3);
            #pragma unroll
            for (int half = 0; half < 2; half++){
                const int r = r0 + 8*half;
                float v0 = a[half*2 + 0], v1 = a[half*2 + 1];
                if (EPI == 1){
                    v0 += biasN[blockIdx.x*128 + c0];     v0 = fmaxf(v0, 0.f);
                    v1 += biasN[blockIdx.x*128 + c0 + 1]; v1 = fmaxf(v1, 0.f);
                }
                if (EPI == 2){
                    v0 += biasN[blockIdx.x*128 + c0]     + rb[(size_t)r*N + c0];
                    v1 += biasN[blockIdx.x*128 + c0 + 1] + rb[(size_t)r*N + c0 + 1];
                }
                if (EPI == 3){
                    v0 += rb[(size_t)r*N + c0];
                    v1 += rb[(size_t)r*N + c0 + 1];
                }
                if (ROUND){ v0 = roundtf(v0); v1 = roundtf(v1); }
                float2 o = {v0, v1};
                *(float2*)(Cb + (size_t)r*N + c0) = o;
            }
        }
}

// ---------------------------------------------------------------------------
// BD_pre: BD[bh][i][m] = Qr[bh][i] . rk[m][h*64..]
// ---------------------------------------------------------------------------
__global__ __launch_bounds__(256, 1) void bd_async(
    const float* __restrict__ Qr, const float* __restrict__ rk, float* __restrict__ BD)
{
    extern __shared__ float sm[];
    const int bh = blockIdx.z, h = bh & 15;
    float acc[64];
    #pragma unroll
    for (int i = 0; i < 64; i++) acc[i] = 0.f;
    gemm_mainloop(Qr + ((size_t)bh*TT + blockIdx.y*128)*DHD, DHD,
                  rk + (size_t)blockIdx.x*128*DD + h*DHD, DD, DHD, acc, sm);

    const int lane = threadIdx.x & 31, w = threadIdx.x >> 5;
    const int wm = (w >> 2) * 64, wn = (w & 3) * 32;
    float* Cb = BD + ((size_t)bh*TT + blockIdx.y*128)*TT + blockIdx.x*128;
    #pragma unroll
    for (int mi = 0; mi < 4; mi++)
        #pragma unroll
        for (int ni = 0; ni < 4; ni++){
            const float* a = acc + (mi*4 + ni)*4;
            const int r0 = wm + mi*16 + (lane >> 2);
            const int c0 = wn + ni*8 + 2*(lane & 3);
            #pragma unroll
            for (int half = 0; half < 2; half++){
                float2 o = {a[half*2], a[half*2 + 1]};
                *(float2*)(Cb + (size_t)(r0 + 8*half)*TT + c0) = o;
            }
        }
}

// ---------------------------------------------------------------------------
// Fused flash attention with rel-shift (ldmatrix fragments, Q in registers).
// grid (8 i-tiles, 128 bh), 256 threads.
// smem floats: Qs[128*68]=8704 | Ks[2][128*68]=17408 | Vs[64*132]=8448 | Ps[128*132]=16896
// ---------------------------------------------------------------------------
__global__ __launch_bounds__(256, 1) void flash_attn(
    const float* __restrict__ Qw, const float* __restrict__ qkv,
    const float* __restrict__ vT, const float* __restrict__ BD,
    float* __restrict__ attn)
{
    extern __shared__ float sm[];
    float* Qs = sm;                 // [128][68]
    float* Ks = sm + 8704;          // [2][128][68]
    float* Vs = sm + 26112;         // [64][132]
    float* Ps = sm + 34560;         // [128][132]
    const uint32_t qB = s2u(Qs), kB = s2u(Ks), vB = s2u(Vs), pB = s2u(Ps);

    const int bh = blockIdx.y, b = bh >> 4, h = bh & 15;
    const int i0 = blockIdx.x * 128;
    const int tid = threadIdx.x, lane = tid & 31, w = tid >> 5;
    const int gr = lane >> 2, tg = lane & 3;
    const int wm = w * 16;

    // ldmatrix lane address components
    const int arow = (lane & 7) + ((lane >> 3) & 1)*8;
    const int acol = (lane >> 4) * 4;
    const int brow = (lane & 7) + ((lane >> 4) & 1)*8;
    const int bcol = ((lane >> 3) & 1) * 4;

    const int klr = tid >> 1, kc0 = (tid & 1) * 32;
    const int vr  = tid >> 2, vc0 = (tid & 3) * 32;

    const float* Qsrc = Qw + ((size_t)bh*TT + i0 + klr)*DHD + kc0;
    const float* Ksrc = qkv + ((size_t)klr*BB + b)*(3*DD) + DD + h*DHD + kc0;
    const size_t kRowStride = (size_t)BB*3*DD;
    const float* Vsrc = vT + ((size_t)bh*DHD + vr)*TT + vc0;

    auto issueQ = [&](){
        uint32_t d = qB + (uint32_t)(klr*68 + kc0)*4;
        #pragma unroll
        for (int u = 0; u < 8; u++) cp16(d + u*16, Qsrc + u*4);
    };
    auto issueK = [&](int slot, int jt){
        if (jt < 8){
            const float* src = Ksrc + (size_t)jt*128*kRowStride;
            uint32_t d = kB + (uint32_t)(slot*8704 + klr*68 + kc0)*4;
            #pragma unroll
            for (int u = 0; u < 8; u++) cp16(d + u*16, src + u*4);
        }
    };
    auto issueV = [&](int jt){
        if (jt < 8){
            const float* src = Vsrc + jt*128;
            uint32_t d = vB + (uint32_t)(vr*132 + vc0)*4;
            #pragma unroll
            for (int u = 0; u < 8; u++) cp16(d + u*16, src + u*4);
        }
    };

    issueQ(); issueK(0, 0); CP_COMMIT();
    issueV(0);              CP_COMMIT();
    issueK(1, 1);           CP_COMMIT();

    float m_lo = -1e30f, m_hi = -1e30f, l_lo = 0.f, l_hi = 0.f;
    float acc_o[8][4];
    #pragma unroll
    for (int i = 0; i < 8; i++)
        #pragma unroll
        for (int e = 0; e < 4; e++) acc_o[i][e] = 0.f;

    uint32_t af_q[8][4];   // Q fragments, preloaded after first wait

    const float* bdb = BD + (size_t)bh * TT * TT;
    const int i_lo = i0 + wm + gr, i_hi = i_lo + 8;

    for (int t = 0; t < 8; t++){
        CP_WAIT(2);
        __syncthreads();
        if (t == 0){
            const uint32_t qf = qB + (uint32_t)((wm + arow)*68 + acol)*4;
            #pragma unroll
            for (int kk = 0; kk < 8; kk++)
                ldm4(af_q[kk], qf + (uint32_t)(kk*8)*4);
        }
        // ---- scores: S = Q @ K^T over K=64 ----
        float acc_s[16][4];
        #pragma unroll
        for (int ni = 0; ni < 16; ni++)
            #pragma unroll
            for (int e = 0; e < 4; e++) acc_s[ni][e] = 0.f;
        const uint32_t kf = kB + (uint32_t)((t & 1)*8704 + brow*68 + bcol)*4;
        #pragma unroll
        for (int kk = 0; kk < 8; kk++){
            #pragma unroll
            for (int p = 0; p < 8; p++){
                uint32_t q[4];
                ldm4(q, kf + (uint32_t)(p*16*68 + kk*8)*4);
                mma8(acc_s[2*p],     af_q[kk], q);
                mma8(acc_s[2*p + 1], af_q[kk], q + 2);
            }
        }
        // ---- rel-shift BD add + scale + online softmax ----
        const int j0 = t * 128;
        float smax_lo = -1e30f, smax_hi = -1e30f;
        #pragma unroll
        for (int ni = 0; ni < 16; ni++){
            #pragma unroll
            for (int e = 0; e < 4; e++){
                const int i = (e < 2) ? i_lo : i_hi;
                const int j = j0 + ni*8 + 2*tg + (e & 1);
                const int d = j - i;
                float bd;
                if (d <= 0)      bd = bdb[(size_t)i*TT + d + (TT - 1)];
                else if (d == 1) bd = 0.f;
                else             bd = bdb[(size_t)(i+1)*TT + d - 2];
                const float v = (acc_s[ni][e] + bd) * 0.125f;
                acc_s[ni][e] = v;
                if (e < 2) smax_lo = fmaxf(smax_lo, v);
                else       smax_hi = fmaxf(smax_hi, v);
            }
        }
        smax_lo = fmaxf(smax_lo, __shfl_xor_sync(0xffffffffu, smax_lo, 1));
        smax_lo = fmaxf(smax_lo, __shfl_xor_sync(0xffffffffu, smax_lo, 2));
        smax_hi = fmaxf(smax_hi, __shfl_xor_sync(0xffffffffu, smax_hi, 1));
        smax_hi = fmaxf(smax_hi, __shfl_xor_sync(0xffffffffu, smax_hi, 2));
        const float mn_lo = fmaxf(m_lo, smax_lo);
        const float mn_hi = fmaxf(m_hi, smax_hi);
        const float corr_lo = __expf(m_lo - mn_lo);
        const float corr_hi = __expf(m_hi - mn_hi);
        m_lo = mn_lo; m_hi = mn_hi;
        float ls_lo = 0.f, ls_hi = 0.f;
        #pragma unroll
        for (int ni = 0; ni < 16; ni++){
            float p0 = __expf(acc_s[ni][0] - mn_lo);
            float p1 = __expf(acc_s[ni][1] - mn_lo);
            float p2 = __expf(acc_s[ni][2] - mn_hi);
            float p3 = __expf(acc_s[ni][3] - mn_hi);
            ls_lo += p0 + p1; ls_hi += p2 + p3;
            float2 lo = { roundtf(p0), roundtf(p1) };
            float2 hi = { roundtf(p2), roundtf(p3) };
            *(float2*)(Ps + (wm + gr)*132 + ni*8 + 2*tg)     = lo;
            *(float2*)(Ps + (wm + gr + 8)*132 + ni*8 + 2*tg) = hi;
        }
        l_lo = l_lo * corr_lo + ls_lo;
        l_hi = l_hi * corr_hi + ls_hi;
        #pragma unroll
        for (int ni = 0; ni < 8; ni++){
            acc_o[ni][0] *= corr_lo; acc_o[ni][1] *= corr_lo;
            acc_o[ni][2] *= corr_hi; acc_o[ni][3] *= corr_hi;
        }
        __syncwarp();
        CP_WAIT(1);
        __syncthreads();
        // ---- PV: O += P @ V^T over K=128 ----
        const uint32_t pf = pB + (uint32_t)((wm + arow)*132 + acol)*4;
        const uint32_t vf = vB + (uint32_t)(brow*132 + bcol)*4;
        #pragma unroll
        for (int kk = 0; kk < 16; kk++){
            uint32_t af[4];
            ldm4(af, pf + (uint32_t)(kk*8)*4);
            #pragma unroll
            for (int p = 0; p < 4; p++){
                uint32_t q[4];
                ldm4(q, vf + (uint32_t)(p*16*132 + kk*8)*4);
                mma8(acc_o[2*p],     af, q);
                mma8(acc_o[2*p + 1], af, q + 2);
            }
        }
        __syncthreads();
        issueV(t + 1);        CP_COMMIT();
        issueK(t & 1, t + 2); CP_COMMIT();
    }

    // final: normalize rows, round, store
    l_lo += __shfl_xor_sync(0xffffffffu, l_lo, 1);
    l_lo += __shfl_xor_sync(0xffffffffu, l_lo, 2);
    l_hi += __shfl_xor_sync(0xffffffffu, l_hi, 1);
    l_hi += __shfl_xor_sync(0xffffffffu, l_hi, 2);
    const float inv_lo = 1.0f / l_lo, inv_hi = 1.0f / l_hi;
    float* out_lo = attn + ((size_t)i_lo*BB + b)*DD + h*DHD;
    float* out_hi = attn + ((size_t)i_hi*BB + b)*DD + h*DHD;
    #pragma unroll
    for (int ni = 0; ni < 8; ni++){
        const int c = ni*8 + 2*tg;
        float2 lo = { roundtf(acc_o[ni][0]*inv_lo), roundtf(acc_o[ni][1]*inv_lo) };
        float2 hi = { roundtf(acc_o[ni][2]*inv_hi), roundtf(acc_o[ni][3]*inv_hi) };
        *(float2*)(out_lo + c) = lo;
        *(float2*)(out_hi + c) = hi;
    }
}

// ---------------------------------------------------------------------------
// LayerNorm (tf32-rounded output)
// ---------------------------------------------------------------------------
__global__ __launch_bounds__(256) void ln_kernel(
    const float* __restrict__ x, const float* __restrict__ wp,
    const float* __restrict__ bparam, float* __restrict__ out)
{
    const int row = blockIdx.x;
    const int tid = threadIdx.x;
    const float4* xr = reinterpret_cast<const float4*>(x + (size_t)row * DD);
    float4 v = xr[tid];
    float s  = v.x + v.y + v.z + v.w;
    float sq = v.x*v.x + v.y*v.y + v.z*v.z + v.w*v.w;
    #pragma unroll
    for (int o = 16; o > 0; o >>= 1) {
        s  += __shfl_xor_sync(0xffffffffu, s,  o);
        sq += __shfl_xor_sync(0xffffffffu, sq, o);
    }
    __shared__ float ss[8], ssq[8];
    if ((tid & 31) == 0) { ss[tid >> 5] = s; ssq[tid >> 5] = sq; }
    __syncthreads();
    float S = 0.f, SQ = 0.f;
    #pragma unroll
    for (int i = 0; i < 8; i++) { S += ss[i]; SQ += ssq[i]; }
    const float mean = S * (1.0f / DD);
    const float var  = SQ * (1.0f / DD) - mean * mean;
    const float rstd = rsqrtf(var + 1e-5f);
    const float4 wv = reinterpret_cast<const float4*>(wp)[tid];
    const float4 bv = reinterpret_cast<const float4*>(bparam)[tid];
    float4 o;
    o.x = roundtf((v.x - mean) * rstd * wv.x + bv.x);
    o.y = roundtf((v.y - mean) * rstd * wv.y + bv.y);
    o.z = roundtf((v.z - mean) * rstd * wv.z + bv.z);
    o.w = roundtf((v.w - mean) * rstd * wv.w + bv.w);
    reinterpret_cast<float4*>(out + (size_t)row * DD)[tid] = o;
}

// ---------------------------------------------------------------------------
// Launch
// ---------------------------------------------------------------------------
extern "C" void kernel_launch(void* const* d_in, const int* in_sizes, int n_in,
                              void* d_out, int out_size)
{
    (void)in_sizes; (void)n_in; (void)out_size;
    const float* x1      = (const float*)d_in[0];
    const float* x2      = (const float*)d_in[1];
    const float* pos     = (const float*)d_in[2];
    const float* ln1_w   = (const float*)d_in[3];
    const float* ln1_b   = (const float*)d_in[4];
    const float* qkv_w   = (const float*)d_in[5];
    const float* r_w     = (const float*)d_in[6];
    const float* r_w_b   = (const float*)d_in[7];
    const float* r_r_b   = (const float*)d_in[8];
    const float* o_w     = (const float*)d_in[9];
    const float* ln2_w   = (const float*)d_in[10];
    const float* ln2_b   = (const float*)d_in[11];
    const float* ffn_w1  = (const float*)d_in[12];
    const float* ffn_b1  = (const float*)d_in[13];
    const float* ffn_w2  = (const float*)d_in[14];
    const float* ffn_b2  = (const float*)d_in[15];

    float* out = (float*)d_out;
    float* y1 = out;
    float* y2 = out + (size_t)TB * DD;

    float *p_ln, *p_qkv, *p_rk, *p_bd, *p_attn, *p_h1;
    float *p_qw, *p_qr, *p_vt, *p_posr, *p_wqkv, *p_wr, *p_wo, *p_wf1, *p_wf2;
    cudaGetSymbolAddress((void**)&p_ln,   g_ln);
    cudaGetSymbolAddress((void**)&p_qkv,  g_qkv);
    cudaGetSymbolAddress((void**)&p_rk,   g_rk);
    cudaGetSymbolAddress((void**)&p_bd,   g_bd);
    cudaGetSymbolAddress((void**)&p_attn, g_attn);
    cudaGetSymbolAddress((void**)&p_h1,   g_h1);
    cudaGetSymbolAddress((void**)&p_qw,   g_qw);
    cudaGetSymbolAddress((void**)&p_qr,   g_qr);
    cudaGetSymbolAddress((void**)&p_vt,   g_vt);
    cudaGetSymbolAddress((void**)&p_posr, g_posr);
    cudaGetSymbolAddress((void**)&p_wqkv, g_wqkv);
    cudaGetSymbolAddress((void**)&p_wr,   g_wr);
    cudaGetSymbolAddress((void**)&p_wo,   g_wo);
    cudaGetSymbolAddress((void**)&p_wf1,  g_wf1);
    cudaGetSymbolAddress((void**)&p_wf2,  g_wf2);

    const int GEMM_SMEM  = 81920;
    const int FLASH_SMEM = 205824;
    cudaFuncSetAttribute(gemm_async<0,1>, cudaFuncAttributeMaxDynamicSharedMemorySize, GEMM_SMEM);
    cudaFuncSetAttribute(gemm_async<1,1>, cudaFuncAttributeMaxDynamicSharedMemorySize, GEMM_SMEM);
    cudaFuncSetAttribute(gemm_async<2,0>, cudaFuncAttributeMaxDynamicSharedMemorySize, GEMM_SMEM);
    cudaFuncSetAttribute(gemm_async<3,0>, cudaFuncAttributeMaxDynamicSharedMemorySize, GEMM_SMEM);
    cudaFuncSetAttribute(bd_async,        cudaFuncAttributeMaxDynamicSharedMemorySize, GEMM_SMEM);
    cudaFuncSetAttribute(flash_attn,      cudaFuncAttributeMaxDynamicSharedMemorySize, FLASH_SMEM);

    // 0. all weight/pos tf32 pre-rounds in one launch
    CvtArgs ca;
    ca.src[0] = qkv_w;  ca.dst[0] = p_wqkv;
    ca.src[1] = r_w;    ca.dst[1] = p_wr;
    ca.src[2] = o_w;    ca.dst[2] = p_wo;
    ca.src[3] = ffn_w1; ca.dst[3] = p_wf1;
    ca.src[4] = ffn_w2; ca.dst[4] = p_wf2;
    ca.src[5] = pos;    ca.dst[5] = p_posr;
    cvt_multi<<<14336, 256>>>(ca);
    // 1. LN1(x2)
    ln_kernel<<<TB, 256>>>(x2, ln1_w, ln1_b, p_ln);
    // 2. qkv = ln @ qkv_w^T
    gemm_async<0,1><<<dim3(24, 64), 256, GEMM_SMEM>>>(p_ln, p_wqkv, p_qkv, 3*DD, DD, nullptr, nullptr);
    // 3. r_k = pos @ r_w^T
    gemm_async<0,1><<<dim3(8, 8), 256, GEMM_SMEM>>>(p_posr, p_wr, p_rk, DD, DD, nullptr, nullptr);
    // 4. Q prep + V transpose
    qprep_kernel<<<8192, 256>>>(p_qkv, r_w_b, r_r_b, p_qw, p_qr);
    vtrans<<<dim3(16, 128), 256>>>(p_qkv, p_vt);
    // 5. BD_pre
    bd_async<<<dim3(8, 8, BH), 256, GEMM_SMEM>>>(p_qr, p_rk, p_bd);
    // 6. fused attention
    flash_attn<<<dim3(8, BH), 256, FLASH_SMEM>>>(p_qw, p_qkv, p_vt, p_bd, p_attn);
    // 7. y1 = attn @ o_w^T + x1
    gemm_async<3,0><<<dim3(8, 64), 256, GEMM_SMEM>>>(p_attn, p_wo, y1, DD, DD, nullptr, x1);
    // 8. LN2(y1)
    ln_kernel<<<TB, 256>>>(y1, ln2_w, ln2_b, p_ln);
    // 9. h1 = relu(ln @ ffn_w1^T + b1)
    gemm_async<1,1><<<dim3(32, 64), 256, GEMM_SMEM>>>(p_ln, p_wf1, p_h1, FFD, DD, ffn_b1, nullptr);
    // 10. y2 = h1 @ ffn_w2^T + b2 + x2
    gemm_async<2,0><<<dim3(8, 64), 256, GEMM_SMEM>>>(p_h1, p_wf2, y2, DD, FFD, ffn_b2, x2);
}